// round 10
// baseline (speedup 1.0000x reference)
#include <cuda_runtime.h>
#include <cuda_fp16.h>
#include <math.h>
#include <stdint.h>

// ---------------- problem constants ----------------
#define HH      14
#define LL      196            // H*W
#define EMBED   768
#define DIMM    3072           // 4*EMBED
#define DINN    6144           // 2*DIM
#define DTRr    192
#define DSTt    16
#define DCONV   4
#define BATCH   2
#define MROWS   392            // BATCH*LL
#define XPROJ_N 224            // DTR + 2*DST

// ---------------- fp32 scratch ----------------
__device__ float g_xe [MROWS * EMBED];
__device__ float g_xm [MROWS * DIMM];
__device__ float g_xr [MROWS * 2 * DINN];
__device__ float g_xs [MROWS * DINN];
__device__ float g_dbl[MROWS * XPROJ_N];
__device__ float g_dt [MROWS * DINN];
__device__ float g_xp [MROWS * EMBED];
__device__ float g_split[8 * MROWS * 768];   // split-K partials
__device__ int   g_sp[LL];
__device__ int   g_ra[LL];
__device__ int   g_bd[LL];

// ---------------- fp16 activation mirrors (GEMM A-operands) ----------------
__device__ __half h_col [MROWS * EMBED];
__device__ __half h_xln [MROWS * DIMM];
__device__ __half h_xs  [MROWS * DINN];
__device__ __half h_dbl [MROWS * XPROJ_N];
__device__ __half h_y   [MROWS * DINN];
__device__ __half h_xm  [MROWS * DIMM];

// ---------------- helpers ----------------
__device__ __forceinline__ float sigmoidf_(float v) { return 1.0f / (1.0f + expf(-v)); }
__device__ __forceinline__ float softplusf_(float v) {
    return v > 0.0f ? v + log1pf(expf(-v)) : log1pf(expf(v));
}
__device__ __forceinline__ void mma_f16(float* c, const uint32_t* a, const uint32_t* b) {
    asm volatile(
        "mma.sync.aligned.m16n8k16.row.col.f32.f16.f16.f32 "
        "{%0,%1,%2,%3}, {%4,%5,%6,%7}, {%8,%9}, {%0,%1,%2,%3};"
        : "+f"(c[0]), "+f"(c[1]), "+f"(c[2]), "+f"(c[3])
        : "r"(a[0]), "r"(a[1]), "r"(a[2]), "r"(a[3]), "r"(b[0]), "r"(b[1]));
}
__device__ __forceinline__ void ldsm4(uint32_t& r0, uint32_t& r1, uint32_t& r2, uint32_t& r3,
                                      uint32_t addr) {
    asm volatile("ldmatrix.sync.aligned.m8n8.x4.shared.b16 {%0,%1,%2,%3}, [%4];"
                 : "=r"(r0), "=r"(r1), "=r"(r2), "=r"(r3) : "r"(addr));
}
__device__ __forceinline__ void cp_async16h(uint32_t dst, const __half* src) {
    asm volatile("cp.async.ca.shared.global [%0], [%1], 16;"
                 :: "r"(dst), "l"(__cvta_generic_to_global(src)) : "memory");
}
__device__ __forceinline__ void cp_async16f(uint32_t dst, const float* src) {
    asm volatile("cp.async.ca.shared.global [%0], [%1], 16;"
                 :: "r"(dst), "l"(__cvta_generic_to_global(src)) : "memory");
}
__device__ __forceinline__ void cp_commit() {
    asm volatile("cp.async.commit_group;" ::: "memory");
}
__device__ __forceinline__ void cp_wait1() {
    asm volatile("cp.async.wait_group 1;" ::: "memory");
}

// ========== fp16-mma GEMM, fp32 B converted in-kernel: C[M,N]=A[M,K]*B[N,K]^T ==========
// A: fp16 [M,lda]. B: fp32 [N,K] (weights). tile 128x128, k16, 3-stage cp.async pipeline.
// 256 threads = 8 warps (2M x 4N), warp tile 64x32. split-K via gridDim.z.
#define TMt 128
#define TNt 128
#define NST 3
#define HPITCH 24                          // halves per fp16 smem row (48B)
#define PITCHF 20                          // floats per fp32 staging row (80B)
#define ATILE_B (TMt * HPITCH * 2)         // 6144 B fp16 tile (A or B)
#define BSTG_B  (TMt * PITCHF * 4)         // 10240 B fp32 staging
#define STAGE_B (2 * ATILE_B + BSTG_B)     // 22528 B
#define SMEMSZ  (NST * STAGE_B)            // 67584 B

__global__ __launch_bounds__(256, 2)
void tc_gemm_nt(const __half* __restrict__ A, int lda,
                const float* __restrict__ B,
                float* __restrict__ C, __half* __restrict__ Ch,
                int M, int N, int K,
                const float* __restrict__ bias,
                int act, int beta)
{
    extern __shared__ char smem[];
    const uint32_t sbase = (uint32_t)__cvta_generic_to_shared(smem);
    const int tid  = threadIdx.x;
    const int wid  = tid >> 5;
    const int lane = tid & 31;
    const int g = lane >> 2;
    const int t = lane & 3;
    const int bm0 = blockIdx.y * TMt;
    const int bn0 = blockIdx.x * TNt;
    const int wm0 = (wid >> 2) * 64;
    const int wn0 = (wid & 3) * 32;

    const int kchunk = K / gridDim.z;
    const int koff   = blockIdx.z * kchunk;
    const int ns     = kchunk >> 4;
    C += (size_t)blockIdx.z * M * N;

    // ldmatrix lane offsets (bytes within fp16 operand tiles)
    const int q  = lane >> 3;
    const int ri = lane & 7;
    uint32_t aoff[4], boff[2];
#pragma unroll
    for (int mi = 0; mi < 4; mi++)
        aoff[mi] = (uint32_t)(((wm0 + mi * 16 + (q & 1) * 8 + ri) * HPITCH + (q >> 1) * 8) * 2);
#pragma unroll
    for (int nj = 0; nj < 2; nj++)
        boff[nj] = (uint32_t)(((wn0 + nj * 16 + (q >> 1) * 8 + ri) * HPITCH + (q & 1) * 8) * 2);

    // load mapping: 2 threads per row, 8 elements each
    const int lrow = tid >> 1;            // 0..127
    const int lk8  = (tid & 1) * 8;
    int ar = bm0 + lrow; if (ar > M - 1) ar = M - 1;
    int br = bn0 + lrow; if (br > N - 1) br = N - 1;
    const __half* pa = A + (size_t)ar * lda + koff + lk8;
    const float*  pb = B + (size_t)br * K + koff + lk8;
    const uint32_t aso  = (uint32_t)((lrow * HPITCH + lk8) * 2);     // A fp16 dest
    const uint32_t bso  = (uint32_t)((lrow * PITCHF + lk8) * 4);     // B fp32 staging dest
    const uint32_t bho  = (uint32_t)((lrow * HPITCH + lk8) * 2);     // B fp16 dest

    auto issue = [&](int s) {
        const uint32_t base = sbase + (uint32_t)(s % NST) * STAGE_B;
        cp_async16h(base + aso, pa + s * 16);
        cp_async16f(base + 2 * ATILE_B + bso,      pb + s * 16);
        cp_async16f(base + 2 * ATILE_B + bso + 16, pb + s * 16 + 4);
        cp_commit();
    };

    float c[4][4][4];
#pragma unroll
    for (int mi = 0; mi < 4; mi++)
#pragma unroll
        for (int ni = 0; ni < 4; ni++)
#pragma unroll
            for (int r = 0; r < 4; r++) c[mi][ni][r] = 0.0f;

    // prologue
#pragma unroll
    for (int s = 0; s < NST - 1; s++) {
        if (s < ns) issue(s); else cp_commit();
    }

    for (int s = 0; s < ns; s++) {
        cp_wait1();
        __syncthreads();
        if (s + NST - 1 < ns) issue(s + NST - 1); else cp_commit();

        char* sm = smem + (size_t)(s % NST) * STAGE_B;
        // convert this stage's B fp32 staging -> fp16 tile
        {
            const float* stg = reinterpret_cast<const float*>(sm + 2 * ATILE_B);
            float4 v0 = *reinterpret_cast<const float4*>(stg + lrow * PITCHF + lk8);
            float4 v1 = *reinterpret_cast<const float4*>(stg + lrow * PITCHF + lk8 + 4);
            __half2 h[4];
            h[0] = __floats2half2_rn(v0.x, v0.y); h[1] = __floats2half2_rn(v0.z, v0.w);
            h[2] = __floats2half2_rn(v1.x, v1.y); h[3] = __floats2half2_rn(v1.z, v1.w);
            *reinterpret_cast<uint4*>(sm + ATILE_B + bho) = *reinterpret_cast<uint4*>(h);
        }
        __syncthreads();

        const uint32_t abase = sbase + (uint32_t)(s % NST) * STAGE_B;
        const uint32_t bbase = abase + ATILE_B;
        uint32_t a[4][4], b[4][2];
#pragma unroll
        for (int mi = 0; mi < 4; mi++)
            ldsm4(a[mi][0], a[mi][1], a[mi][2], a[mi][3], abase + aoff[mi]);
#pragma unroll
        for (int nj = 0; nj < 2; nj++) {
            uint32_t r0, r1, r2, r3;
            ldsm4(r0, r1, r2, r3, bbase + boff[nj]);
            b[2 * nj][0] = r0; b[2 * nj][1] = r1;
            b[2 * nj + 1][0] = r2; b[2 * nj + 1][1] = r3;
        }
#pragma unroll
        for (int mi = 0; mi < 4; mi++)
#pragma unroll
            for (int ni = 0; ni < 4; ni++)
                mma_f16(c[mi][ni], a[mi], b[ni]);
    }

    // epilogue
#pragma unroll
    for (int mi = 0; mi < 4; mi++) {
        const int row0 = bm0 + wm0 + mi * 16 + g;
#pragma unroll
        for (int ni = 0; ni < 4; ni++) {
            const int col0 = bn0 + wn0 + ni * 8 + 2 * t;
#pragma unroll
            for (int r = 0; r < 4; r++) {
                const int row = row0 + ((r >> 1) << 3);
                const int col = col0 + (r & 1);
                if (row < M && col < N) {
                    float v = c[mi][ni][r];
                    if (bias) v += bias[col];
                    if (act == 1) v = softplusf_(v);
                    float* p = C + (size_t)row * N + col;
                    if (beta) v += *p;
                    *p = v;
                    if (Ch) Ch[(size_t)row * N + col] = __float2half(v);
                }
            }
        }
    }
}

// ---------------- split-K reduce (+bias, + fp16 mirror) ----------------
__global__ void reduce_split_kernel(const float* __restrict__ sp,
                                    float* __restrict__ C, __half* __restrict__ Ch,
                                    const float* __restrict__ bias,
                                    int nsplit, int MN, int N)
{
    int idx = blockIdx.x * blockDim.x + threadIdx.x;
    if (idx >= MN) return;
    float s = 0.0f;
    for (int i = 0; i < nsplit; i++) s += sp[(size_t)i * MN + idx];
    if (bias) s += bias[idx % N];
    C[idx] = s;
    if (Ch) Ch[idx] = __float2half(s);
}

// ---------------- index tables (numpy double-precision exact) ----------------
__global__ void compute_indices_kernel() {
    __shared__ double sdd[LL];
    __shared__ double saa[LL];
    __shared__ int    cand[202];
    __shared__ unsigned char seen[LL];
    const int tid = threadIdx.x;
    const double TWO_PI = 2.0 * 3.14159265358979323846;

    if (tid < 202) {
        int r = 0, rem = tid;
        for (;;) {
            int c = (2 * r > 8) ? 2 * r : 8;
            if (rem < c) break;
            rem -= c; r++;
        }
        int nang = (2 * r > 8) ? 2 * r : 8;
        double step = TWO_PI / (double)nang;
        double ang = (double)rem * step;
        double hh = 7.0 + (double)r * cos(ang);
        double ww = 7.0 + (double)r * sin(ang);
        int h = (int)hh;
        int w = (int)ww;
        cand[tid] = (h >= 0 && h < HH && w >= 0 && w < HH) ? (h * HH + w) : -1;
    }
    if (tid < LL) {
        seen[tid] = 0;
        int h = tid / HH, w = tid % HH;
        double dy = (double)(h - 7), dx = (double)(w - 7);
        sdd[tid] = sqrt(dy * dy + dx * dx);
        saa[tid] = atan2(dy, dx);
    }
    __syncthreads();

    if (tid == 0) {
        int cnt = 0;
        for (int i = 0; i < 202; i++) {
            int c = cand[i];
            if (c >= 0 && !seen[c]) { seen[c] = 1; g_sp[cnt++] = c; }
        }
        for (int i = 0; i < LL; i++)
            if (!seen[i]) g_sp[cnt++] = i;
        int bc = 0;
        for (int i = 0; i < LL; i++) {
            int h = i / HH, w = i % HH;
            if (h == 0 || h == HH - 1 || w == 0 || w == HH - 1) g_bd[bc++] = i;
        }
        for (int i = 0; i < LL; i++) {
            int h = i / HH, w = i % HH;
            if (!(h == 0 || h == HH - 1 || w == 0 || w == HH - 1)) g_bd[bc++] = i;
        }
    }
    if (tid < LL) {
        double di = sdd[tid], ai = saa[tid];
        int rank = 0;
        for (int j = 0; j < LL; j++) {
            double dj = sdd[j], aj = saa[j];
            bool before = (dj > di) ||
                          (dj == di && (aj < ai || (aj == ai && j < tid)));
            rank += before ? 1 : 0;
        }
        g_ra[rank] = tid;
    }
}

// ---------------- im2col (fp16 out) ----------------
__global__ void im2col_kernel(const float* __restrict__ x) {
    int idx = blockIdx.x * blockDim.x + threadIdx.x;
    if (idx >= MROWS * EMBED) return;
    int m = idx / EMBED;
    int k = idx % EMBED;
    int b = m / LL, l = m % LL;
    int ph = l / HH, pw = l % HH;
    int c = k / 256, rem = k % 256;
    int i = rem / 16, j = rem % 16;
    h_col[idx] = __float2half(
        x[(((size_t)(b * 3 + c) * 224) + (ph * 16 + i)) * 224 + (pw * 16 + j)]);
}

// ---------------- add pos_embed + abcde projection ----------------
__global__ void add_pos_ab_kernel(const float* __restrict__ pos_embed,
                                  const float* __restrict__ abcde_features,
                                  const float* __restrict__ abcde_w,
                                  const float* __restrict__ abcde_b)
{
    int idx = blockIdx.x * blockDim.x + threadIdx.x;
    if (idx >= MROWS * EMBED) return;
    int m = idx / EMBED;
    int e = idx % EMBED;
    int b = m / LL;
    float ab = abcde_b[e];
#pragma unroll
    for (int k = 0; k < 5; k++)
        ab += abcde_features[b * 5 + k] * abcde_w[e * 5 + k];
    int l = m % LL;
    g_xe[idx] += pos_embed[l * EMBED + e] + ab;
}

// ---------------- gather 4 orderings into xm ----------------
__global__ void gather_kernel() {
    int idx = blockIdx.x * blockDim.x + threadIdx.x;
    if (idx >= MROWS * DIMM) return;
    int m = idx / DIMM;
    int c = idx % DIMM;
    int b = m / LL, l = m % LL;
    int s = c / EMBED, e = c % EMBED;
    int src_l = (s == 0) ? g_sp[l] : (s == 1) ? g_ra[l] : (s == 2) ? g_bd[l] : l;
    g_xm[idx] = g_xe[((size_t)(b * LL + src_l)) * EMBED + e];
}

// ---------------- layernorm (fp32 in; optional fp32 / fp16 outs) ----------------
__global__ void ln_kernel(const float* __restrict__ in,
                          float* __restrict__ out_f, __half* __restrict__ out_h,
                          const float* __restrict__ w, const float* __restrict__ b,
                          int width)
{
    __shared__ float red[256];
    __shared__ float s_mean, s_rstd;
    const int row = blockIdx.x;
    const float* x = in + (size_t)row * width;
    float s = 0.0f;
    for (int j = threadIdx.x; j < width; j += 256) s += x[j];
    red[threadIdx.x] = s; __syncthreads();
    for (int off = 128; off > 0; off >>= 1) {
        if (threadIdx.x < off) red[threadIdx.x] += red[threadIdx.x + off];
        __syncthreads();
    }
    if (threadIdx.x == 0) s_mean = red[0] / (float)width;
    __syncthreads();
    float m = s_mean;
    float vs = 0.0f;
    for (int j = threadIdx.x; j < width; j += 256) {
        float d = x[j] - m; vs += d * d;
    }
    red[threadIdx.x] = vs; __syncthreads();
    for (int off = 128; off > 0; off >>= 1) {
        if (threadIdx.x < off) red[threadIdx.x] += red[threadIdx.x + off];
        __syncthreads();
    }
    if (threadIdx.x == 0) s_rstd = rsqrtf(red[0] / (float)width + 1e-5f);
    __syncthreads();
    float r = s_rstd;
    for (int j = threadIdx.x; j < width; j += 256) {
        float v = (x[j] - m) * r * w[j] + b[j];
        if (out_f) out_f[(size_t)row * width + j] = v;
        if (out_h) out_h[(size_t)row * width + j] = __float2half(v);
    }
}

// ---------------- causal depthwise conv + bias + silu (fp32 + fp16 out) ----------------
__global__ void conv_silu_kernel(const float* __restrict__ conv_w,
                                 const float* __restrict__ conv_b)
{
    int idx = blockIdx.x * blockDim.x + threadIdx.x;
    if (idx >= MROWS * DINN) return;
    int row = idx / DINN;
    int d   = idx % DINN;
    int b = row / LL, t = row % LL;
    float acc = conv_b[d];
#pragma unroll
    for (int j = 0; j < DCONV; j++) {
        int tt = t - (DCONV - 1) + j;
        if (tt >= 0)
            acc += conv_w[d * DCONV + j] * g_xr[((size_t)(b * LL + tt)) * (2 * DINN) + d];
    }
    float v = acc * sigmoidf_(acc);
    g_xs[idx] = v;
    h_xs[idx] = __float2half(v);
}

// ---------------- selective scan (fp16 y out) ----------------
__global__ void scan_kernel(const float* __restrict__ A_log,
                            const float* __restrict__ D_param)
{
    const int g = blockIdx.x * blockDim.x + threadIdx.x;
    const int n  = g & 15;
    const int dg = g >> 4;
    const int d  = dg % DINN;
    const int b  = dg / DINN;

    const float Alog2 = -expf(A_log[d * DSTt + n]) * 1.4426950408889634f;
    const float Dd = D_param[d];

    float st = 0.0f;
#pragma unroll 1
    for (int t = 0; t < LL; t++) {
        const size_t row = (size_t)(b * LL + t);
        const float dtv = g_dt[row * DINN + d];
        const float xv  = g_xs[row * DINN + d];
        const float Bv  = g_dbl[row * XPROJ_N + DTRr + n];
        const float Cv  = g_dbl[row * XPROJ_N + DTRr + DSTt + n];
        st = st * exp2f(dtv * Alog2) + dtv * Bv * xv;
        float p = st * Cv;
        p += __shfl_xor_sync(0xffffffffu, p, 1, 16);
        p += __shfl_xor_sync(0xffffffffu, p, 2, 16);
        p += __shfl_xor_sync(0xffffffffu, p, 4, 16);
        p += __shfl_xor_sync(0xffffffffu, p, 8, 16);
        if (n == 0) {
            float res = g_xr[row * (2 * DINN) + DINN + d];
            float y = (p + xv * Dd) * (res * sigmoidf_(res));
            h_y[row * DINN + d] = __float2half(y);
        }
    }
}

// ---------------- final mean over L ----------------
__global__ void mean_kernel(float* __restrict__ out) {
    int idx = blockIdx.x * blockDim.x + threadIdx.x;
    if (idx >= BATCH * EMBED) return;
    int b = idx / EMBED, e = idx % EMBED;
    float s = 0.0f;
    for (int l = 0; l < LL; l++)
        s += g_xp[((size_t)(b * LL + l)) * EMBED + e];
    out[idx] = s / (float)LL;
}

// ---------------- host helpers ----------------
static inline void launch_gemm(const __half* A, int lda, const float* B,
                               float* C, __half* Ch,
                               int M, int N, int K,
                               const float* bias, int act, int beta, int splitk = 1)
{
    dim3 grid((N + TNt - 1) / TNt, (M + TMt - 1) / TMt, splitk);
    tc_gemm_nt<<<grid, 256, SMEMSZ>>>(A, lda, B, C, Ch, M, N, K, bias, act, beta);
}

extern "C" void kernel_launch(void* const* d_in, const int* in_sizes, int n_in,
                              void* d_out, int out_size)
{
    const bool dictOrder = (in_sizes[14] == 2 * DINN * DSTt);

    const float* x          = (const float*)d_in[0];
    const float* abcde_feat = (const float*)d_in[1];
    const float* patch_w    = (const float*)d_in[2];
    const float* patch_b    = (const float*)d_in[3];
    const float* pos_embed  = (const float*)d_in[4];
    const float* abcde_w    = (const float*)d_in[5];
    const float* abcde_b    = (const float*)d_in[6];
    const float* ln_w       = (const float*)d_in[7];
    const float* ln_b       = (const float*)d_in[8];
    const float* in_proj_w  = (const float*)d_in[9];
    const float* conv_w     = (const float*)d_in[10];
    const float* conv_b     = (const float*)d_in[11];
    const float* x_proj_w   = (const float*)d_in[12];
    const float* dt_proj_w  = (const float*)d_in[13];
    const float* dt_proj_b  = dictOrder ? (const float*)d_in[21] : (const float*)d_in[14];
    const float* A_log      = dictOrder ? (const float*)d_in[14] : (const float*)d_in[15];
    const float* D_param    = dictOrder ? (const float*)d_in[15] : (const float*)d_in[16];
    const float* out_proj_w = dictOrder ? (const float*)d_in[16] : (const float*)d_in[17];
    const float* proj_w     = dictOrder ? (const float*)d_in[17] : (const float*)d_in[18];
    const float* proj_b     = dictOrder ? (const float*)d_in[18] : (const float*)d_in[19];
    const float* norm_w     = dictOrder ? (const float*)d_in[19] : (const float*)d_in[20];
    const float* norm_b     = dictOrder ? (const float*)d_in[20] : (const float*)d_in[21];

    float* out = (float*)d_out;

    float *p_xm, *p_xr, *p_xs, *p_dbl, *p_dt, *p_xe, *p_xp, *p_split;
    cudaGetSymbolAddress((void**)&p_xm,  g_xm);
    cudaGetSymbolAddress((void**)&p_xr,  g_xr);
    cudaGetSymbolAddress((void**)&p_xs,  g_xs);
    cudaGetSymbolAddress((void**)&p_dbl, g_dbl);
    cudaGetSymbolAddress((void**)&p_dt,  g_dt);
    cudaGetSymbolAddress((void**)&p_xe,  g_xe);
    cudaGetSymbolAddress((void**)&p_xp,  g_xp);
    cudaGetSymbolAddress((void**)&p_split, g_split);
    __half *ph_col, *ph_xln, *ph_xs, *ph_dbl, *ph_y, *ph_xm;
    cudaGetSymbolAddress((void**)&ph_col, h_col);
    cudaGetSymbolAddress((void**)&ph_xln, h_xln);
    cudaGetSymbolAddress((void**)&ph_xs,  h_xs);
    cudaGetSymbolAddress((void**)&ph_dbl, h_dbl);
    cudaGetSymbolAddress((void**)&ph_y,   h_y);
    cudaGetSymbolAddress((void**)&ph_xm,  h_xm);

    cudaFuncSetAttribute(tc_gemm_nt, cudaFuncAttributeMaxDynamicSharedMemorySize, SMEMSZ);

    // 1. index tables
    compute_indices_kernel<<<1, 256>>>();

    // 2. patch embedding
    im2col_kernel<<<(MROWS * EMBED + 255) / 256, 256>>>(x);
    launch_gemm(ph_col, EMBED, patch_w, p_xe, nullptr,
                MROWS, EMBED, EMBED, patch_b, 0, 0);
    add_pos_ab_kernel<<<(MROWS * EMBED + 255) / 256, 256>>>(pos_embed, abcde_feat, abcde_w, abcde_b);
    gather_kernel<<<(MROWS * DIMM + 255) / 256, 256>>>();

    // 3. mamba layers
    for (int l = 0; l < 2; l++) {
        const float* w_in  = in_proj_w  + (size_t)l * 2 * DINN * DIMM;
        const float* w_cv  = conv_w     + (size_t)l * DINN * DCONV;
        const float* b_cv  = conv_b     + (size_t)l * DINN;
        const float* w_xp  = x_proj_w   + (size_t)l * XPROJ_N * DINN;
        const float* w_dt  = dt_proj_w  + (size_t)l * DINN * DTRr;
        const float* b_dt  = dt_proj_b  + (size_t)l * DINN;
        const float* w_out = out_proj_w + (size_t)l * DIMM * DINN;
        const float* Al    = A_log      + (size_t)l * DINN * DSTt;
        const float* Dl    = D_param    + (size_t)l * DINN;

        ln_kernel<<<MROWS, 256>>>(p_xm, nullptr, ph_xln,
                                  ln_w + l * DIMM, ln_b + l * DIMM, DIMM);

        // in_proj: [392,3072] x [12288,3072]^T -> fp32 xr
        launch_gemm(ph_xln, DIMM, w_in, p_xr, nullptr,
                    MROWS, 2 * DINN, DIMM, nullptr, 0, 0);

        conv_silu_kernel<<<(MROWS * DINN + 255) / 256, 256>>>(w_cv, b_cv);

        // x_proj: split-K 8 -> reduce -> dbl (fp32 + fp16)
        launch_gemm(ph_xs, DINN, w_xp, p_split, nullptr,
                    MROWS, XPROJ_N, DINN, nullptr, 0, 0, 8);
        reduce_split_kernel<<<(MROWS * XPROJ_N + 255) / 256, 256>>>(
            p_split, p_dbl, ph_dbl, nullptr, 8, MROWS * XPROJ_N, XPROJ_N);

        // dt_proj + bias + softplus -> fp32 dt
        launch_gemm(ph_dbl, XPROJ_N, w_dt, p_dt, nullptr,
                    MROWS, DINN, DTRr, b_dt, 1, 0);

        scan_kernel<<<(BATCH * DINN * DSTt) / 256, 256>>>(Al, Dl);

        // out_proj + residual accumulate into xm (+ fp16 mirror)
        launch_gemm(ph_y, DINN, w_out, p_xm, ph_xm,
                    MROWS, DIMM, DINN, nullptr, 0, 1);
    }

    // 4. final projection (split-K 4) + LN + mean
    launch_gemm(ph_xm, DIMM, proj_w, p_split, nullptr,
                MROWS, EMBED, DIMM, nullptr, 0, 0, 4);
    reduce_split_kernel<<<(MROWS * EMBED + 255) / 256, 256>>>(
        p_split, p_xp, nullptr, proj_b, 4, MROWS * EMBED, EMBED);
    ln_kernel<<<MROWS, 256>>>(p_xp, p_xp, nullptr, norm_w, norm_b, EMBED);
    mean_kernel<<<(BATCH * EMBED + 255) / 256, 256>>>(out);

    (void)n_in; (void)out_size;
}

// round 11
// speedup vs baseline: 1.2228x; 1.2228x over previous
#include <cuda_runtime.h>
#include <cuda_fp16.h>
#include <math.h>
#include <stdint.h>

// ---------------- problem constants ----------------
#define HH      14
#define LL      196            // H*W
#define EMBED   768
#define DIMM    3072           // 4*EMBED
#define DINN    6144           // 2*DIM
#define DTRr    192
#define DSTt    16
#define DCONV   4
#define BATCH   2
#define MROWS   392            // BATCH*LL
#define XPROJ_N 224            // DTR + 2*DST

// ---------------- fp32 scratch ----------------
__device__ float g_xe [MROWS * EMBED];
__device__ float g_xm [MROWS * DIMM];
__device__ float g_xr [MROWS * 2 * DINN];
__device__ float g_xs [MROWS * DINN];
__device__ float g_dbl[MROWS * XPROJ_N];
__device__ float g_dt [MROWS * DINN];
__device__ float g_xp [MROWS * EMBED];
__device__ float g_split[8 * MROWS * 768];   // split-K partials
__device__ int   g_sp[LL];
__device__ int   g_ra[LL];
__device__ int   g_bd[LL];

// ---------------- fp16 activation mirrors (GEMM A-operands) ----------------
__device__ __half h_col [MROWS * EMBED];
__device__ __half h_xln [MROWS * DIMM];
__device__ __half h_xs  [MROWS * DINN];
__device__ __half h_dbl [MROWS * XPROJ_N];
__device__ __half h_y   [MROWS * DINN];
__device__ __half h_xm  [MROWS * DIMM];
// fp16 weights
__device__ __half h_patchw[EMBED * EMBED];
__device__ __half h_inw  [2 * 2 * DINN * DIMM];
__device__ __half h_xpw  [2 * XPROJ_N * DINN];
__device__ __half h_dtw  [2 * DINN * DTRr];
__device__ __half h_outw [2 * DIMM * DINN];
__device__ __half h_projw[EMBED * DIMM];

// ---------------- helpers ----------------
__device__ __forceinline__ float sigmoidf_(float v) { return 1.0f / (1.0f + expf(-v)); }
__device__ __forceinline__ float softplusf_(float v) {
    return v > 0.0f ? v + log1pf(expf(-v)) : log1pf(expf(v));
}
__device__ __forceinline__ void mma_f16(float* c, const uint32_t* a, const uint32_t* b) {
    asm volatile(
        "mma.sync.aligned.m16n8k16.row.col.f32.f16.f16.f32 "
        "{%0,%1,%2,%3}, {%4,%5,%6,%7}, {%8,%9}, {%0,%1,%2,%3};"
        : "+f"(c[0]), "+f"(c[1]), "+f"(c[2]), "+f"(c[3])
        : "r"(a[0]), "r"(a[1]), "r"(a[2]), "r"(a[3]), "r"(b[0]), "r"(b[1]));
}
__device__ __forceinline__ void ldsm4(uint32_t& r0, uint32_t& r1, uint32_t& r2, uint32_t& r3,
                                      uint32_t addr) {
    asm volatile("ldmatrix.sync.aligned.m8n8.x4.shared.b16 {%0,%1,%2,%3}, [%4];"
                 : "=r"(r0), "=r"(r1), "=r"(r2), "=r"(r3) : "r"(addr));
}
__device__ __forceinline__ void cp_async16(uint32_t dst, const __half* src) {
    asm volatile("cp.async.ca.shared.global [%0], [%1], 16;"
                 :: "r"(dst), "l"(__cvta_generic_to_global(src)) : "memory");
}
__device__ __forceinline__ void cp_commit() {
    asm volatile("cp.async.commit_group;" ::: "memory");
}
__device__ __forceinline__ void cp_wait2() {
    asm volatile("cp.async.wait_group 2;" ::: "memory");
}

// ================= fp16 tensor-core GEMM, cp.async 4-stage (R8-proven) =================
// C[M,N] = A[M,K] * B[N,K]^T. tile 128x128 x k16; 256 thr = 8 warps (2M x 4N), warp 64x32.
// split-K via gridDim.z (partials at C + z*M*N).
#define TMt 128
#define TNt 128
#define NST 4
#define HPITCH 24                          // halves per smem row (48B), conflict-free ldmatrix
#define ATILE_B (TMt * HPITCH * 2)         // 6144 B per operand per stage
#define STAGE_B (2 * ATILE_B)              // 12288 B
#define SMEMSZ  (NST * STAGE_B)            // 49152 B

__global__ __launch_bounds__(256, 2)
void tc_gemm_nt(const __half* __restrict__ A, int lda,
                const __half* __restrict__ B,
                float* __restrict__ C, __half* __restrict__ Ch,
                int M, int N, int K,
                const float* __restrict__ bias,
                int act, int beta)
{
    extern __shared__ char smem[];
    const uint32_t sbase = (uint32_t)__cvta_generic_to_shared(smem);
    const int tid  = threadIdx.x;
    const int wid  = tid >> 5;
    const int lane = tid & 31;
    const int g = lane >> 2;
    const int t = lane & 3;
    const int bm0 = blockIdx.y * TMt;
    const int bn0 = blockIdx.x * TNt;
    const int wm0 = (wid >> 2) * 64;
    const int wn0 = (wid & 3) * 32;

    const int kchunk = K / gridDim.z;
    const int koff   = blockIdx.z * kchunk;
    const int ns     = kchunk >> 4;
    C += (size_t)blockIdx.z * M * N;

    const int q  = lane >> 3;
    const int ri = lane & 7;
    uint32_t aoff[4], boff[2];
#pragma unroll
    for (int mi = 0; mi < 4; mi++)
        aoff[mi] = (uint32_t)(((wm0 + mi * 16 + (q & 1) * 8 + ri) * HPITCH + (q >> 1) * 8) * 2);
#pragma unroll
    for (int nj = 0; nj < 2; nj++)
        boff[nj] = (uint32_t)(((wn0 + nj * 16 + (q >> 1) * 8 + ri) * HPITCH + (q & 1) * 8) * 2);

    const int lrow = tid >> 1;
    const int lk8  = (tid & 1) * 8;
    int ar = bm0 + lrow; if (ar > M - 1) ar = M - 1;
    int br = bn0 + lrow; if (br > N - 1) br = N - 1;
    const __half* pa = A + (size_t)ar * lda + koff + lk8;
    const __half* pb = B + (size_t)br * K + koff + lk8;
    const uint32_t soff = (uint32_t)((lrow * HPITCH + lk8) * 2);

    auto issue = [&](int s) {
        const uint32_t base = sbase + (uint32_t)(s % NST) * STAGE_B;
        cp_async16(base + soff, pa + s * 16);
        cp_async16(base + ATILE_B + soff, pb + s * 16);
        cp_commit();
    };

    float c[4][4][4];
#pragma unroll
    for (int mi = 0; mi < 4; mi++)
#pragma unroll
        for (int ni = 0; ni < 4; ni++)
#pragma unroll
            for (int r = 0; r < 4; r++) c[mi][ni][r] = 0.0f;

#pragma unroll
    for (int s = 0; s < NST - 1; s++) {
        if (s < ns) issue(s); else cp_commit();
    }

    for (int s = 0; s < ns; s++) {
        cp_wait2();
        __syncthreads();
        if (s + NST - 1 < ns) issue(s + NST - 1); else cp_commit();

        const uint32_t abase = sbase + (uint32_t)(s % NST) * STAGE_B;
        const uint32_t bbase = abase + ATILE_B;
        uint32_t a[4][4], b[4][2];
#pragma unroll
        for (int mi = 0; mi < 4; mi++)
            ldsm4(a[mi][0], a[mi][1], a[mi][2], a[mi][3], abase + aoff[mi]);
#pragma unroll
        for (int nj = 0; nj < 2; nj++) {
            uint32_t r0, r1, r2, r3;
            ldsm4(r0, r1, r2, r3, bbase + boff[nj]);
            b[2 * nj][0] = r0; b[2 * nj][1] = r1;
            b[2 * nj + 1][0] = r2; b[2 * nj + 1][1] = r3;
        }
#pragma unroll
        for (int mi = 0; mi < 4; mi++)
#pragma unroll
            for (int ni = 0; ni < 4; ni++)
                mma_f16(c[mi][ni], a[mi], b[ni]);
    }

#pragma unroll
    for (int mi = 0; mi < 4; mi++) {
        const int row0 = bm0 + wm0 + mi * 16 + g;
#pragma unroll
        for (int ni = 0; ni < 4; ni++) {
            const int col0 = bn0 + wn0 + ni * 8 + 2 * t;
#pragma unroll
            for (int r = 0; r < 4; r++) {
                const int row = row0 + ((r >> 1) << 3);
                const int col = col0 + (r & 1);
                if (row < M && col < N) {
                    float v = c[mi][ni][r];
                    if (bias) v += bias[col];
                    if (act == 1) v = softplusf_(v);
                    float* p = C + (size_t)row * N + col;
                    if (beta) v += *p;
                    *p = v;
                    if (Ch) Ch[(size_t)row * N + col] = __float2half(v);
                }
            }
        }
    }
}

// ---------------- split-K reduce (+bias, + fp16 mirror) ----------------
__global__ void reduce_split_kernel(const float* __restrict__ sp,
                                    float* __restrict__ C, __half* __restrict__ Ch,
                                    const float* __restrict__ bias,
                                    int nsplit, int MN, int N)
{
    int idx = blockIdx.x * blockDim.x + threadIdx.x;
    if (idx >= MN) return;
    float s = 0.0f;
    for (int i = 0; i < nsplit; i++) s += sp[(size_t)i * MN + idx];
    if (bias) s += bias[idx % N];
    C[idx] = s;
    if (Ch) Ch[idx] = __float2half(s);
}

// ---------------- fused fp32->fp16 weight conversion (all 6 tensors, 1 launch) ----------------
// unit = 8 elements (32B read, 16B write). Segment sizes are compile-time constants.
#define U_PATCH ((EMBED * EMBED) / 8)
#define U_IN    ((2 * 2 * DINN * DIMM) / 8)
#define U_XP    ((2 * XPROJ_N * DINN) / 8)
#define U_DT    ((2 * DINN * DTRr) / 8)
#define U_OUT   ((2 * DIMM * DINN) / 8)
#define U_PROJ  ((EMBED * DIMM) / 8)
#define C0 U_PATCH
#define C1 (C0 + U_IN)
#define C2 (C1 + U_XP)
#define C3 (C2 + U_DT)
#define C4 (C3 + U_OUT)
#define C5 (C4 + U_PROJ)

__global__ void f2h_all_kernel(const float* __restrict__ s0, const float* __restrict__ s1,
                               const float* __restrict__ s2, const float* __restrict__ s3,
                               const float* __restrict__ s4, const float* __restrict__ s5,
                               __half* __restrict__ d0, __half* __restrict__ d1,
                               __half* __restrict__ d2, __half* __restrict__ d3,
                               __half* __restrict__ d4, __half* __restrict__ d5)
{
    const long stride = (long)gridDim.x * blockDim.x;
    auto unit = [&](long u) {
        const float* s; __half* d; long o;
        if      (u < C0) { s = s0; d = d0; o = u; }
        else if (u < C1) { s = s1; d = d1; o = u - C0; }
        else if (u < C2) { s = s2; d = d2; o = u - C1; }
        else if (u < C3) { s = s3; d = d3; o = u - C2; }
        else if (u < C4) { s = s4; d = d4; o = u - C3; }
        else             { s = s5; d = d5; o = u - C4; }
        const float4* p = reinterpret_cast<const float4*>(s) + 2 * o;
        float4 a = p[0], b = p[1];
        __half2 h[4];
        h[0] = __floats2half2_rn(a.x, a.y); h[1] = __floats2half2_rn(a.z, a.w);
        h[2] = __floats2half2_rn(b.x, b.y); h[3] = __floats2half2_rn(b.z, b.w);
        reinterpret_cast<uint4*>(d)[o] = *reinterpret_cast<uint4*>(h);
    };
    long u = (long)blockIdx.x * blockDim.x + threadIdx.x;
    for (; u + 3 * stride < C5; u += 4 * stride) {
        unit(u); unit(u + stride); unit(u + 2 * stride); unit(u + 3 * stride);
    }
    for (; u < C5; u += stride) unit(u);
}

// ---------------- index tables (numpy double-precision exact) ----------------
__global__ void compute_indices_kernel() {
    __shared__ double sdd[LL];
    __shared__ double saa[LL];
    __shared__ int    cand[202];
    __shared__ unsigned char seen[LL];
    const int tid = threadIdx.x;
    const double TWO_PI = 2.0 * 3.14159265358979323846;

    if (tid < 202) {
        int r = 0, rem = tid;
        for (;;) {
            int c = (2 * r > 8) ? 2 * r : 8;
            if (rem < c) break;
            rem -= c; r++;
        }
        int nang = (2 * r > 8) ? 2 * r : 8;
        double step = TWO_PI / (double)nang;
        double ang = (double)rem * step;
        double hh = 7.0 + (double)r * cos(ang);
        double ww = 7.0 + (double)r * sin(ang);
        int h = (int)hh;
        int w = (int)ww;
        cand[tid] = (h >= 0 && h < HH && w >= 0 && w < HH) ? (h * HH + w) : -1;
    }
    if (tid < LL) {
        seen[tid] = 0;
        int h = tid / HH, w = tid % HH;
        double dy = (double)(h - 7), dx = (double)(w - 7);
        sdd[tid] = sqrt(dy * dy + dx * dx);
        saa[tid] = atan2(dy, dx);
    }
    __syncthreads();

    if (tid == 0) {
        int cnt = 0;
        for (int i = 0; i < 202; i++) {
            int c = cand[i];
            if (c >= 0 && !seen[c]) { seen[c] = 1; g_sp[cnt++] = c; }
        }
        for (int i = 0; i < LL; i++)
            if (!seen[i]) g_sp[cnt++] = i;
        int bc = 0;
        for (int i = 0; i < LL; i++) {
            int h = i / HH, w = i % HH;
            if (h == 0 || h == HH - 1 || w == 0 || w == HH - 1) g_bd[bc++] = i;
        }
        for (int i = 0; i < LL; i++) {
            int h = i / HH, w = i % HH;
            if (!(h == 0 || h == HH - 1 || w == 0 || w == HH - 1)) g_bd[bc++] = i;
        }
    }
    if (tid < LL) {
        double di = sdd[tid], ai = saa[tid];
        int rank = 0;
        for (int j = 0; j < LL; j++) {
            double dj = sdd[j], aj = saa[j];
            bool before = (dj > di) ||
                          (dj == di && (aj < ai || (aj == ai && j < tid)));
            rank += before ? 1 : 0;
        }
        g_ra[rank] = tid;
    }
}

// ---------------- im2col (fp16 out) ----------------
__global__ void im2col_kernel(const float* __restrict__ x) {
    int idx = blockIdx.x * blockDim.x + threadIdx.x;
    if (idx >= MROWS * EMBED) return;
    int m = idx / EMBED;
    int k = idx % EMBED;
    int b = m / LL, l = m % LL;
    int ph = l / HH, pw = l % HH;
    int c = k / 256, rem = k % 256;
    int i = rem / 16, j = rem % 16;
    h_col[idx] = __float2half(
        x[(((size_t)(b * 3 + c) * 224) + (ph * 16 + i)) * 224 + (pw * 16 + j)]);
}

// ---------------- fused gather: xm = concat4(xe[perm] + pos[perm] + ab) ----------------
__global__ void gather_fused_kernel(const float* __restrict__ pos_embed,
                                    const float* __restrict__ abcde_features,
                                    const float* __restrict__ abcde_w,
                                    const float* __restrict__ abcde_b)
{
    int idx = blockIdx.x * blockDim.x + threadIdx.x;
    if (idx >= MROWS * DIMM) return;
    int m = idx / DIMM;
    int c = idx % DIMM;
    int b = m / LL, l = m % LL;
    int s = c / EMBED, e = c % EMBED;
    int src_l = (s == 0) ? g_sp[l] : (s == 1) ? g_ra[l] : (s == 2) ? g_bd[l] : l;
    float ab = abcde_b[e];
#pragma unroll
    for (int k = 0; k < 5; k++)
        ab += abcde_features[b * 5 + k] * abcde_w[e * 5 + k];
    g_xm[idx] = g_xe[((size_t)(b * LL + src_l)) * EMBED + e]
              + pos_embed[src_l * EMBED + e] + ab;
}

// ---------------- layernorm (fp32 in; optional fp32 / fp16 outs) ----------------
__global__ void ln_kernel(const float* __restrict__ in,
                          float* __restrict__ out_f, __half* __restrict__ out_h,
                          const float* __restrict__ w, const float* __restrict__ b,
                          int width)
{
    __shared__ float red[256];
    __shared__ float s_mean, s_rstd;
    const int row = blockIdx.x;
    const float* x = in + (size_t)row * width;
    float s = 0.0f;
    for (int j = threadIdx.x; j < width; j += 256) s += x[j];
    red[threadIdx.x] = s; __syncthreads();
    for (int off = 128; off > 0; off >>= 1) {
        if (threadIdx.x < off) red[threadIdx.x] += red[threadIdx.x + off];
        __syncthreads();
    }
    if (threadIdx.x == 0) s_mean = red[0] / (float)width;
    __syncthreads();
    float m = s_mean;
    float vs = 0.0f;
    for (int j = threadIdx.x; j < width; j += 256) {
        float d = x[j] - m; vs += d * d;
    }
    red[threadIdx.x] = vs; __syncthreads();
    for (int off = 128; off > 0; off >>= 1) {
        if (threadIdx.x < off) red[threadIdx.x] += red[threadIdx.x + off];
        __syncthreads();
    }
    if (threadIdx.x == 0) s_rstd = rsqrtf(red[0] / (float)width + 1e-5f);
    __syncthreads();
    float r = s_rstd;
    for (int j = threadIdx.x; j < width; j += 256) {
        float v = (x[j] - m) * r * w[j] + b[j];
        if (out_f) out_f[(size_t)row * width + j] = v;
        if (out_h) out_h[(size_t)row * width + j] = __float2half(v);
    }
}

// ---------------- causal depthwise conv + bias + silu (fp32 + fp16 out) ----------------
__global__ void conv_silu_kernel(const float* __restrict__ conv_w,
                                 const float* __restrict__ conv_b)
{
    int idx = blockIdx.x * blockDim.x + threadIdx.x;
    if (idx >= MROWS * DINN) return;
    int row = idx / DINN;
    int d   = idx % DINN;
    int b = row / LL, t = row % LL;
    float acc = conv_b[d];
#pragma unroll
    for (int j = 0; j < DCONV; j++) {
        int tt = t - (DCONV - 1) + j;
        if (tt >= 0)
            acc += conv_w[d * DCONV + j] * g_xr[((size_t)(b * LL + tt)) * (2 * DINN) + d];
    }
    float v = acc * sigmoidf_(acc);
    g_xs[idx] = v;
    h_xs[idx] = __float2half(v);
}

// ---------------- selective scan (fp16 y out) ----------------
__global__ void scan_kernel(const float* __restrict__ A_log,
                            const float* __restrict__ D_param)
{
    const int g = blockIdx.x * blockDim.x + threadIdx.x;
    const int n  = g & 15;
    const int dg = g >> 4;
    const int d  = dg % DINN;
    const int b  = dg / DINN;

    const float Alog2 = -expf(A_log[d * DSTt + n]) * 1.4426950408889634f;
    const float Dd = D_param[d];

    float st = 0.0f;
#pragma unroll 1
    for (int t = 0; t < LL; t++) {
        const size_t row = (size_t)(b * LL + t);
        const float dtv = g_dt[row * DINN + d];
        const float xv  = g_xs[row * DINN + d];
        const float Bv  = g_dbl[row * XPROJ_N + DTRr + n];
        const float Cv  = g_dbl[row * XPROJ_N + DTRr + DSTt + n];
        st = st * exp2f(dtv * Alog2) + dtv * Bv * xv;
        float p = st * Cv;
        p += __shfl_xor_sync(0xffffffffu, p, 1, 16);
        p += __shfl_xor_sync(0xffffffffu, p, 2, 16);
        p += __shfl_xor_sync(0xffffffffu, p, 4, 16);
        p += __shfl_xor_sync(0xffffffffu, p, 8, 16);
        if (n == 0) {
            float res = g_xr[row * (2 * DINN) + DINN + d];
            float y = (p + xv * Dd) * (res * sigmoidf_(res));
            h_y[row * DINN + d] = __float2half(y);
        }
    }
}

// ---------------- final mean over L ----------------
__global__ void mean_kernel(float* __restrict__ out) {
    int idx = blockIdx.x * blockDim.x + threadIdx.x;
    if (idx >= BATCH * EMBED) return;
    int b = idx / EMBED, e = idx % EMBED;
    float s = 0.0f;
    for (int l = 0; l < LL; l++)
        s += g_xp[((size_t)(b * LL + l)) * EMBED + e];
    out[idx] = s / (float)LL;
}

// ---------------- host helpers ----------------
static inline void launch_gemm(const __half* A, int lda, const __half* B,
                               float* C, __half* Ch,
                               int M, int N, int K,
                               const float* bias, int act, int beta, int splitk = 1)
{
    dim3 grid((N + TNt - 1) / TNt, (M + TMt - 1) / TMt, splitk);
    tc_gemm_nt<<<grid, 256, SMEMSZ>>>(A, lda, B, C, Ch, M, N, K, bias, act, beta);
}

extern "C" void kernel_launch(void* const* d_in, const int* in_sizes, int n_in,
                              void* d_out, int out_size)
{
    const bool dictOrder = (in_sizes[14] == 2 * DINN * DSTt);

    const float* x          = (const float*)d_in[0];
    const float* abcde_feat = (const float*)d_in[1];
    const float* patch_w    = (const float*)d_in[2];
    const float* patch_b    = (const float*)d_in[3];
    const float* pos_embed  = (const float*)d_in[4];
    const float* abcde_w    = (const float*)d_in[5];
    const float* abcde_b    = (const float*)d_in[6];
    const float* ln_w       = (const float*)d_in[7];
    const float* ln_b       = (const float*)d_in[8];
    const float* in_proj_w  = (const float*)d_in[9];
    const float* conv_w     = (const float*)d_in[10];
    const float* conv_b     = (const float*)d_in[11];
    const float* x_proj_w   = (const float*)d_in[12];
    const float* dt_proj_w  = (const float*)d_in[13];
    const float* dt_proj_b  = dictOrder ? (const float*)d_in[21] : (const float*)d_in[14];
    const float* A_log      = dictOrder ? (const float*)d_in[14] : (const float*)d_in[15];
    const float* D_param    = dictOrder ? (const float*)d_in[15] : (const float*)d_in[16];
    const float* out_proj_w = dictOrder ? (const float*)d_in[16] : (const float*)d_in[17];
    const float* proj_w     = dictOrder ? (const float*)d_in[17] : (const float*)d_in[18];
    const float* proj_b     = dictOrder ? (const float*)d_in[18] : (const float*)d_in[19];
    const float* norm_w     = dictOrder ? (const float*)d_in[19] : (const float*)d_in[20];
    const float* norm_b     = dictOrder ? (const float*)d_in[20] : (const float*)d_in[21];

    float* out = (float*)d_out;

    float *p_xm, *p_xr, *p_xs, *p_dbl, *p_dt, *p_xe, *p_xp, *p_split;
    cudaGetSymbolAddress((void**)&p_xm,  g_xm);
    cudaGetSymbolAddress((void**)&p_xr,  g_xr);
    cudaGetSymbolAddress((void**)&p_xs,  g_xs);
    cudaGetSymbolAddress((void**)&p_dbl, g_dbl);
    cudaGetSymbolAddress((void**)&p_dt,  g_dt);
    cudaGetSymbolAddress((void**)&p_xe,  g_xe);
    cudaGetSymbolAddress((void**)&p_xp,  g_xp);
    cudaGetSymbolAddress((void**)&p_split, g_split);
    __half *ph_col, *ph_xln, *ph_xs, *ph_dbl, *ph_y, *ph_xm;
    __half *ph_patchw, *ph_inw, *ph_xpw, *ph_dtw, *ph_outw, *ph_projw;
    cudaGetSymbolAddress((void**)&ph_col, h_col);
    cudaGetSymbolAddress((void**)&ph_xln, h_xln);
    cudaGetSymbolAddress((void**)&ph_xs,  h_xs);
    cudaGetSymbolAddress((void**)&ph_dbl, h_dbl);
    cudaGetSymbolAddress((void**)&ph_y,   h_y);
    cudaGetSymbolAddress((void**)&ph_xm,  h_xm);
    cudaGetSymbolAddress((void**)&ph_patchw, h_patchw);
    cudaGetSymbolAddress((void**)&ph_inw,  h_inw);
    cudaGetSymbolAddress((void**)&ph_xpw,  h_xpw);
    cudaGetSymbolAddress((void**)&ph_dtw,  h_dtw);
    cudaGetSymbolAddress((void**)&ph_outw, h_outw);
    cudaGetSymbolAddress((void**)&ph_projw, h_projw);

    cudaFuncSetAttribute(tc_gemm_nt, cudaFuncAttributeMaxDynamicSharedMemorySize, SMEMSZ);

    // 0. fused weight conversion (1 launch, high-MLP grid-stride)
    f2h_all_kernel<<<2048, 256>>>(patch_w, in_proj_w, x_proj_w, dt_proj_w, out_proj_w, proj_w,
                                  ph_patchw, ph_inw, ph_xpw, ph_dtw, ph_outw, ph_projw);

    // 1. index tables
    compute_indices_kernel<<<1, 256>>>();

    // 2. patch embedding + fused pos/ab/gather
    im2col_kernel<<<(MROWS * EMBED + 255) / 256, 256>>>(x);
    launch_gemm(ph_col, EMBED, ph_patchw, p_xe, nullptr,
                MROWS, EMBED, EMBED, patch_b, 0, 0);
    gather_fused_kernel<<<(MROWS * DIMM + 255) / 256, 256>>>(pos_embed, abcde_feat, abcde_w, abcde_b);

    // 3. mamba layers
    for (int l = 0; l < 2; l++) {
        const __half* w_in  = ph_inw  + (size_t)l * 2 * DINN * DIMM;
        const float*  w_cv  = conv_w  + (size_t)l * DINN * DCONV;
        const float*  b_cv  = conv_b  + (size_t)l * DINN;
        const __half* w_xp  = ph_xpw  + (size_t)l * XPROJ_N * DINN;
        const __half* w_dt  = ph_dtw  + (size_t)l * DINN * DTRr;
        const float*  b_dt  = dt_proj_b + (size_t)l * DINN;
        const __half* w_out = ph_outw + (size_t)l * DIMM * DINN;
        const float*  Al    = A_log   + (size_t)l * DINN * DSTt;
        const float*  Dl    = D_param + (size_t)l * DINN;

        ln_kernel<<<MROWS, 256>>>(p_xm, nullptr, ph_xln,
                                  ln_w + l * DIMM, ln_b + l * DIMM, DIMM);

        // in_proj: [392,3072] x [12288,3072]^T -> fp32 xr
        launch_gemm(ph_xln, DIMM, w_in, p_xr, nullptr,
                    MROWS, 2 * DINN, DIMM, nullptr, 0, 0);

        conv_silu_kernel<<<(MROWS * DINN + 255) / 256, 256>>>(w_cv, b_cv);

        // x_proj: split-K 8 -> reduce -> dbl (fp32 + fp16)
        launch_gemm(ph_xs, DINN, w_xp, p_split, nullptr,
                    MROWS, XPROJ_N, DINN, nullptr, 0, 0, 8);
        reduce_split_kernel<<<(MROWS * XPROJ_N + 255) / 256, 256>>>(
            p_split, p_dbl, ph_dbl, nullptr, 8, MROWS * XPROJ_N, XPROJ_N);

        // dt_proj + bias + softplus -> fp32 dt
        launch_gemm(ph_dbl, XPROJ_N, w_dt, p_dt, nullptr,
                    MROWS, DINN, DTRr, b_dt, 1, 0);

        scan_kernel<<<(BATCH * DINN * DSTt) / 256, 256>>>(Al, Dl);

        // out_proj + residual accumulate into xm (+ fp16 mirror)
        launch_gemm(ph_y, DINN, w_out, p_xm, ph_xm,
                    MROWS, DIMM, DINN, nullptr, 0, 1);
    }

    // 4. final projection (split-K 4) + LN + mean
    launch_gemm(ph_xm, DIMM, ph_projw, p_split, nullptr,
                MROWS, EMBED, DIMM, nullptr, 0, 0, 4);
    reduce_split_kernel<<<(MROWS * EMBED + 255) / 256, 256>>>(
        p_split, p_xp, nullptr, proj_b, 4, MROWS * EMBED, EMBED);
    ln_kernel<<<MROWS, 256>>>(p_xp, p_xp, nullptr, norm_w, norm_b, EMBED);
    mean_kernel<<<(BATCH * EMBED + 255) / 256, 256>>>(out);

    (void)n_in; (void)out_size;
}

// round 13
// speedup vs baseline: 1.2754x; 1.0431x over previous
#include <cuda_runtime.h>
#include <cuda_fp16.h>
#include <math.h>
#include <stdint.h>

// ---------------- problem constants ----------------
#define HH      14
#define LL      196            // H*W
#define EMBED   768
#define DIMM    3072           // 4*EMBED
#define DINN    6144           // 2*DIM
#define DTRr    192
#define DSTt    16
#define DCONV   4
#define BATCH   2
#define MROWS   392            // BATCH*LL
#define XPROJ_N 224            // DTR + 2*DST

// ---------------- fp32 scratch ----------------
__device__ float g_xe [MROWS * EMBED];
__device__ float g_xm [MROWS * DIMM];
__device__ float g_xr [MROWS * 2 * DINN];
__device__ float g_xs [MROWS * DINN];
__device__ float g_dbl[MROWS * XPROJ_N];
__device__ float g_dt [MROWS * DINN];
__device__ float g_xp [MROWS * EMBED];
__device__ float g_split[8 * MROWS * 768];   // split-K partials
__device__ int   g_sp[LL];
__device__ int   g_ra[LL];
__device__ int   g_bd[LL];

// ---------------- fp16 activation mirrors (GEMM A-operands) ----------------
__device__ __half h_col [MROWS * EMBED];
__device__ __half h_xln [MROWS * DIMM];
__device__ __half h_xs  [MROWS * DINN];
__device__ __half h_dbl [MROWS * XPROJ_N];
__device__ __half h_y   [MROWS * DINN];
__device__ __half h_xm  [MROWS * DIMM];
// fp16 weights
__device__ __half h_patchw[EMBED * EMBED];
__device__ __half h_inw  [2 * 2 * DINN * DIMM];
__device__ __half h_xpw  [2 * XPROJ_N * DINN];
__device__ __half h_dtw  [2 * DINN * DTRr];
__device__ __half h_outw [2 * DIMM * DINN];
__device__ __half h_projw[EMBED * DIMM];

// ---------------- helpers ----------------
__device__ __forceinline__ float sigmoidf_(float v) { return 1.0f / (1.0f + expf(-v)); }
__device__ __forceinline__ float softplusf_(float v) {
    return v > 0.0f ? v + log1pf(expf(-v)) : log1pf(expf(v));
}
__device__ __forceinline__ void mma_f16(float* c, const uint32_t* a, const uint32_t* b) {
    asm volatile(
        "mma.sync.aligned.m16n8k16.row.col.f32.f16.f16.f32 "
        "{%0,%1,%2,%3}, {%4,%5,%6,%7}, {%8,%9}, {%0,%1,%2,%3};"
        : "+f"(c[0]), "+f"(c[1]), "+f"(c[2]), "+f"(c[3])
        : "r"(a[0]), "r"(a[1]), "r"(a[2]), "r"(a[3]), "r"(b[0]), "r"(b[1]));
}
__device__ __forceinline__ void ldsm4(uint32_t& r0, uint32_t& r1, uint32_t& r2, uint32_t& r3,
                                      uint32_t addr) {
    asm volatile("ldmatrix.sync.aligned.m8n8.x4.shared.b16 {%0,%1,%2,%3}, [%4];"
                 : "=r"(r0), "=r"(r1), "=r"(r2), "=r"(r3) : "r"(addr));
}
__device__ __forceinline__ void cp_async16(uint32_t dst, const __half* src) {
    asm volatile("cp.async.ca.shared.global [%0], [%1], 16;"
                 :: "r"(dst), "l"(__cvta_generic_to_global(src)) : "memory");
}
__device__ __forceinline__ void cp_commit() {
    asm volatile("cp.async.commit_group;" ::: "memory");
}
__device__ __forceinline__ void cp_wait1() {
    asm volatile("cp.async.wait_group 1;" ::: "memory");
}

// ================= fp16 tensor-core GEMM, k32 stages, 3-deep cp.async =================
// C[M,N] = A[M,K] * B[N,K]^T. tile 128x128 x k32; 256 thr = 8 warps (2M x 4N), warp 64x32.
// split-K via gridDim.z (partials at C + z*M*N). K (chunk) must be divisible by 32.
#define TMt 128
#define TNt 128
#define NST 3
#define HPITCH 40                          // halves per smem row (80B) -> conflict-free ldmatrix
#define ATILE_B (TMt * HPITCH * 2)         // 10240 B per operand per stage
#define STAGE_B (2 * ATILE_B)              // 20480 B
#define SMEMSZ  (NST * STAGE_B)            // 61440 B

__global__ __launch_bounds__(256, 2)
void tc_gemm_nt(const __half* __restrict__ A, int lda,
                const __half* __restrict__ B,
                float* __restrict__ C, __half* __restrict__ Ch,
                int M, int N, int K,
                const float* __restrict__ bias,
                int act, int beta)
{
    extern __shared__ char smem[];
    const uint32_t sbase = (uint32_t)__cvta_generic_to_shared(smem);
    const int tid  = threadIdx.x;
    const int wid  = tid >> 5;
    const int lane = tid & 31;
    const int g = lane >> 2;
    const int t = lane & 3;
    const int bm0 = blockIdx.y * TMt;
    const int bn0 = blockIdx.x * TNt;
    const int wm0 = (wid >> 2) * 64;
    const int wn0 = (wid & 3) * 32;

    const int kchunk = K / gridDim.z;
    const int koff   = blockIdx.z * kchunk;
    const int ns     = kchunk >> 5;        // k32 stages
    C += (size_t)blockIdx.z * M * N;

    // ldmatrix lane offsets (bytes within operand tile)
    const int q  = lane >> 3;
    const int ri = lane & 7;
    uint32_t aoff[4], boff[2];
#pragma unroll
    for (int mi = 0; mi < 4; mi++)
        aoff[mi] = (uint32_t)(((wm0 + mi * 16 + (q & 1) * 8 + ri) * HPITCH + (q >> 1) * 8) * 2);
#pragma unroll
    for (int nj = 0; nj < 2; nj++)
        boff[nj] = (uint32_t)(((wn0 + nj * 16 + (q >> 1) * 8 + ri) * HPITCH + (q & 1) * 8) * 2);

    // cp.async mapping: 2 threads per row, 16 halves (2x16B) each
    const int lrow = tid >> 1;
    const int lk16 = (tid & 1) * 16;
    int ar = bm0 + lrow; if (ar > M - 1) ar = M - 1;
    int br = bn0 + lrow; if (br > N - 1) br = N - 1;
    const __half* pa = A + (size_t)ar * lda + koff + lk16;
    const __half* pb = B + (size_t)br * K + koff + lk16;
    const uint32_t soff = (uint32_t)((lrow * HPITCH + lk16) * 2);

    auto issue = [&](int s) {
        const uint32_t base = sbase + (uint32_t)(s % NST) * STAGE_B;
        cp_async16(base + soff,                pa + s * 32);
        cp_async16(base + soff + 16,           pa + s * 32 + 8);
        cp_async16(base + ATILE_B + soff,      pb + s * 32);
        cp_async16(base + ATILE_B + soff + 16, pb + s * 32 + 8);
        cp_commit();
    };

    float c[4][4][4];
#pragma unroll
    for (int mi = 0; mi < 4; mi++)
#pragma unroll
        for (int ni = 0; ni < 4; ni++)
#pragma unroll
            for (int r = 0; r < 4; r++) c[mi][ni][r] = 0.0f;

#pragma unroll
    for (int s = 0; s < NST - 1; s++) {
        if (s < ns) issue(s); else cp_commit();
    }

    for (int s = 0; s < ns; s++) {
        cp_wait1();
        __syncthreads();
        if (s + NST - 1 < ns) issue(s + NST - 1); else cp_commit();

        const uint32_t abase = sbase + (uint32_t)(s % NST) * STAGE_B;
        const uint32_t bbase = abase + ATILE_B;
#pragma unroll
        for (int ka = 0; ka < 2; ka++) {
            const uint32_t ko = (uint32_t)(ka * 32);   // 16 halves
            uint32_t a[4][4], b[4][2];
#pragma unroll
            for (int mi = 0; mi < 4; mi++)
                ldsm4(a[mi][0], a[mi][1], a[mi][2], a[mi][3], abase + aoff[mi] + ko);
#pragma unroll
            for (int nj = 0; nj < 2; nj++) {
                uint32_t r0, r1, r2, r3;
                ldsm4(r0, r1, r2, r3, bbase + boff[nj] + ko);
                b[2 * nj][0] = r0; b[2 * nj][1] = r1;
                b[2 * nj + 1][0] = r2; b[2 * nj + 1][1] = r3;
            }
#pragma unroll
            for (int mi = 0; mi < 4; mi++)
#pragma unroll
                for (int ni = 0; ni < 4; ni++)
                    mma_f16(c[mi][ni], a[mi], b[ni]);
        }
    }

    // epilogue: float2 / half2 stores (cols 2t,2t+1 adjacent; N always even)
#pragma unroll
    for (int mi = 0; mi < 4; mi++) {
        const int row0 = bm0 + wm0 + mi * 16 + g;
#pragma unroll
        for (int ni = 0; ni < 4; ni++) {
            const int col = bn0 + wn0 + ni * 8 + 2 * t;
            if (col >= N) continue;
#pragma unroll
            for (int h = 0; h < 2; h++) {
                const int row = row0 + 8 * h;
                if (row >= M) continue;
                float v0 = c[mi][ni][2 * h];
                float v1 = c[mi][ni][2 * h + 1];
                if (bias) { v0 += bias[col]; v1 += bias[col + 1]; }
                if (act == 1) { v0 = softplusf_(v0); v1 = softplusf_(v1); }
                float2* p = reinterpret_cast<float2*>(C + (size_t)row * N + col);
                if (beta) { float2 o = *p; v0 += o.x; v1 += o.y; }
                *p = make_float2(v0, v1);
                if (Ch)
                    *reinterpret_cast<__half2*>(Ch + (size_t)row * N + col) =
                        __floats2half2_rn(v0, v1);
            }
        }
    }
}

// ---------------- split-K reduce (+bias, + fp16 mirror) ----------------
__global__ void reduce_split_kernel(const float* __restrict__ sp,
                                    float* __restrict__ C, __half* __restrict__ Ch,
                                    const float* __restrict__ bias,
                                    int nsplit, int MN, int N)
{
    int idx = blockIdx.x * blockDim.x + threadIdx.x;
    if (idx >= MN) return;
    float s = 0.0f;
    for (int i = 0; i < nsplit; i++) s += sp[(size_t)i * MN + idx];
    if (bias) s += bias[idx % N];
    C[idx] = s;
    if (Ch) Ch[idx] = __float2half(s);
}

// ---------------- fused fp32->fp16 weight conversion (all 6 tensors, 1 launch) ----------------
#define U_PATCH ((EMBED * EMBED) / 8)
#define U_IN    ((2 * 2 * DINN * DIMM) / 8)
#define U_XP    ((2 * XPROJ_N * DINN) / 8)
#define U_DT    ((2 * DINN * DTRr) / 8)
#define U_OUT   ((2 * DIMM * DINN) / 8)
#define U_PROJ  ((EMBED * DIMM) / 8)
#define C0 U_PATCH
#define C1 (C0 + U_IN)
#define C2 (C1 + U_XP)
#define C3 (C2 + U_DT)
#define C4 (C3 + U_OUT)
#define C5 (C4 + U_PROJ)

__global__ void f2h_all_kernel(const float* __restrict__ s0, const float* __restrict__ s1,
                               const float* __restrict__ s2, const float* __restrict__ s3,
                               const float* __restrict__ s4, const float* __restrict__ s5,
                               __half* __restrict__ d0, __half* __restrict__ d1,
                               __half* __restrict__ d2, __half* __restrict__ d3,
                               __half* __restrict__ d4, __half* __restrict__ d5)
{
    const long stride = (long)gridDim.x * blockDim.x;
    auto unit = [&](long u) {
        const float* s; __half* d; long o;
        if      (u < C0) { s = s0; d = d0; o = u; }
        else if (u < C1) { s = s1; d = d1; o = u - C0; }
        else if (u < C2) { s = s2; d = d2; o = u - C1; }
        else if (u < C3) { s = s3; d = d3; o = u - C2; }
        else if (u < C4) { s = s4; d = d4; o = u - C3; }
        else             { s = s5; d = d5; o = u - C4; }
        const float4* p = reinterpret_cast<const float4*>(s) + 2 * o;
        float4 a = p[0], b = p[1];
        __half2 h[4];
        h[0] = __floats2half2_rn(a.x, a.y); h[1] = __floats2half2_rn(a.z, a.w);
        h[2] = __floats2half2_rn(b.x, b.y); h[3] = __floats2half2_rn(b.z, b.w);
        reinterpret_cast<uint4*>(d)[o] = *reinterpret_cast<uint4*>(h);
    };
    long u = (long)blockIdx.x * blockDim.x + threadIdx.x;
    for (; u + 3 * stride < C5; u += 4 * stride) {
        unit(u); unit(u + stride); unit(u + 2 * stride); unit(u + 3 * stride);
    }
    for (; u < C5; u += stride) unit(u);
}

// ---------------- index tables (numpy double-precision exact) ----------------
__global__ void compute_indices_kernel() {
    __shared__ double sdd[LL];
    __shared__ double saa[LL];
    __shared__ int    cand[202];
    __shared__ unsigned char seen[LL];
    const int tid = threadIdx.x;
    const double TWO_PI = 2.0 * 3.14159265358979323846;

    if (tid < 202) {
        int r = 0, rem = tid;
        for (;;) {
            int c = (2 * r > 8) ? 2 * r : 8;
            if (rem < c) break;
            rem -= c; r++;
        }
        int nang = (2 * r > 8) ? 2 * r : 8;
        double step = TWO_PI / (double)nang;
        double ang = (double)rem * step;
        double hh = 7.0 + (double)r * cos(ang);
        double ww = 7.0 + (double)r * sin(ang);
        int h = (int)hh;
        int w = (int)ww;
        cand[tid] = (h >= 0 && h < HH && w >= 0 && w < HH) ? (h * HH + w) : -1;
    }
    if (tid < LL) {
        seen[tid] = 0;
        int h = tid / HH, w = tid % HH;
        double dy = (double)(h - 7), dx = (double)(w - 7);
        sdd[tid] = sqrt(dy * dy + dx * dx);
        saa[tid] = atan2(dy, dx);
    }
    __syncthreads();

    if (tid == 0) {
        int cnt = 0;
        for (int i = 0; i < 202; i++) {
            int c = cand[i];
            if (c >= 0 && !seen[c]) { seen[c] = 1; g_sp[cnt++] = c; }
        }
        for (int i = 0; i < LL; i++)
            if (!seen[i]) g_sp[cnt++] = i;
        int bc = 0;
        for (int i = 0; i < LL; i++) {
            int h = i / HH, w = i % HH;
            if (h == 0 || h == HH - 1 || w == 0 || w == HH - 1) g_bd[bc++] = i;
        }
        for (int i = 0; i < LL; i++) {
            int h = i / HH, w = i % HH;
            if (!(h == 0 || h == HH - 1 || w == 0 || w == HH - 1)) g_bd[bc++] = i;
        }
    }
    if (tid < LL) {
        double di = sdd[tid], ai = saa[tid];
        int rank = 0;
        for (int j = 0; j < LL; j++) {
            double dj = sdd[j], aj = saa[j];
            bool before = (dj > di) ||
                          (dj == di && (aj < ai || (aj == ai && j < tid)));
            rank += before ? 1 : 0;
        }
        g_ra[rank] = tid;
    }
}

// ---------------- im2col (fp16 out) ----------------
__global__ void im2col_kernel(const float* __restrict__ x) {
    int idx = blockIdx.x * blockDim.x + threadIdx.x;
    if (idx >= MROWS * EMBED) return;
    int m = idx / EMBED;
    int k = idx % EMBED;
    int b = m / LL, l = m % LL;
    int ph = l / HH, pw = l % HH;
    int c = k / 256, rem = k % 256;
    int i = rem / 16, j = rem % 16;
    h_col[idx] = __float2half(
        x[(((size_t)(b * 3 + c) * 224) + (ph * 16 + i)) * 224 + (pw * 16 + j)]);
}

// ---------------- fused gather: xm = concat4(xe[perm] + pos[perm] + ab) ----------------
__global__ void gather_fused_kernel(const float* __restrict__ pos_embed,
                                    const float* __restrict__ abcde_features,
                                    const float* __restrict__ abcde_w,
                                    const float* __restrict__ abcde_b)
{
    int idx = blockIdx.x * blockDim.x + threadIdx.x;
    if (idx >= MROWS * DIMM) return;
    int m = idx / DIMM;
    int c = idx % DIMM;
    int b = m / LL, l = m % LL;
    int s = c / EMBED, e = c % EMBED;
    int src_l = (s == 0) ? g_sp[l] : (s == 1) ? g_ra[l] : (s == 2) ? g_bd[l] : l;
    float ab = abcde_b[e];
#pragma unroll
    for (int k = 0; k < 5; k++)
        ab += abcde_features[b * 5 + k] * abcde_w[e * 5 + k];
    g_xm[idx] = g_xe[((size_t)(b * LL + src_l)) * EMBED + e]
              + pos_embed[src_l * EMBED + e] + ab;
}

// ---------------- layernorm (fp32 in; optional fp32 / fp16 outs) ----------------
__global__ void ln_kernel(const float* __restrict__ in,
                          float* __restrict__ out_f, __half* __restrict__ out_h,
                          const float* __restrict__ w, const float* __restrict__ b,
                          int width)
{
    __shared__ float red[256];
    __shared__ float s_mean, s_rstd;
    const int row = blockIdx.x;
    const float* x = in + (size_t)row * width;
    float s = 0.0f;
    for (int j = threadIdx.x; j < width; j += 256) s += x[j];
    red[threadIdx.x] = s; __syncthreads();
    for (int off = 128; off > 0; off >>= 1) {
        if (threadIdx.x < off) red[threadIdx.x] += red[threadIdx.x + off];
        __syncthreads();
    }
    if (threadIdx.x == 0) s_mean = red[0] / (float)width;
    __syncthreads();
    float m = s_mean;
    float vs = 0.0f;
    for (int j = threadIdx.x; j < width; j += 256) {
        float d = x[j] - m; vs += d * d;
    }
    red[threadIdx.x] = vs; __syncthreads();
    for (int off = 128; off > 0; off >>= 1) {
        if (threadIdx.x < off) red[threadIdx.x] += red[threadIdx.x + off];
        __syncthreads();
    }
    if (threadIdx.x == 0) s_rstd = rsqrtf(red[0] / (float)width + 1e-5f);
    __syncthreads();
    float r = s_rstd;
    for (int j = threadIdx.x; j < width; j += 256) {
        float v = (x[j] - m) * r * w[j] + b[j];
        if (out_f) out_f[(size_t)row * width + j] = v;
        if (out_h) out_h[(size_t)row * width + j] = __float2half(v);
    }
}

// ---------------- causal depthwise conv + bias + silu (fp32 + fp16 out) ----------------
__global__ void conv_silu_kernel(const float* __restrict__ conv_w,
                                 const float* __restrict__ conv_b)
{
    int idx = blockIdx.x * blockDim.x + threadIdx.x;
    if (idx >= MROWS * DINN) return;
    int row = idx / DINN;
    int d   = idx % DINN;
    int b = row / LL, t = row % LL;
    float acc = conv_b[d];
#pragma unroll
    for (int j = 0; j < DCONV; j++) {
        int tt = t - (DCONV - 1) + j;
        if (tt >= 0)
            acc += conv_w[d * DCONV + j] * g_xr[((size_t)(b * LL + tt)) * (2 * DINN) + d];
    }
    float v = acc * sigmoidf_(acc);
    g_xs[idx] = v;
    h_xs[idx] = __float2half(v);
}

// ---------------- selective scan (fp16 y out) ----------------
__global__ void scan_kernel(const float* __restrict__ A_log,
                            const float* __restrict__ D_param)
{
    const int g = blockIdx.x * blockDim.x + threadIdx.x;
    const int n  = g & 15;
    const int dg = g >> 4;
    const int d  = dg % DINN;
    const int b  = dg / DINN;

    const float Alog2 = -expf(A_log[d * DSTt + n]) * 1.4426950408889634f;
    const float Dd = D_param[d];

    float st = 0.0f;
#pragma unroll 1
    for (int t = 0; t < LL; t++) {
        const size_t row = (size_t)(b * LL + t);
        const float dtv = g_dt[row * DINN + d];
        const float xv  = g_xs[row * DINN + d];
        const float Bv  = g_dbl[row * XPROJ_N + DTRr + n];
        const float Cv  = g_dbl[row * XPROJ_N + DTRr + DSTt + n];
        st = st * exp2f(dtv * Alog2) + dtv * Bv * xv;
        float p = st * Cv;
        p += __shfl_xor_sync(0xffffffffu, p, 1, 16);
        p += __shfl_xor_sync(0xffffffffu, p, 2, 16);
        p += __shfl_xor_sync(0xffffffffu, p, 4, 16);
        p += __shfl_xor_sync(0xffffffffu, p, 8, 16);
        if (n == 0) {
            float res = g_xr[row * (2 * DINN) + DINN + d];
            float y = (p + xv * Dd) * (res * sigmoidf_(res));
            h_y[row * DINN + d] = __float2half(y);
        }
    }
}

// ---------------- final mean over L ----------------
__global__ void mean_kernel(float* __restrict__ out) {
    int idx = blockIdx.x * blockDim.x + threadIdx.x;
    if (idx >= BATCH * EMBED) return;
    int b = idx / EMBED, e = idx % EMBED;
    float s = 0.0f;
    for (int l = 0; l < LL; l++)
        s += g_xp[((size_t)(b * LL + l)) * EMBED + e];
    out[idx] = s / (float)LL;
}

// ---------------- host helpers ----------------
static inline void launch_gemm(const __half* A, int lda, const __half* B,
                               float* C, __half* Ch,
                               int M, int N, int K,
                               const float* bias, int act, int beta, int splitk = 1)
{
    dim3 grid((N + TNt - 1) / TNt, (M + TMt - 1) / TMt, splitk);
    tc_gemm_nt<<<grid, 256, SMEMSZ>>>(A, lda, B, C, Ch, M, N, K, bias, act, beta);
}

extern "C" void kernel_launch(void* const* d_in, const int* in_sizes, int n_in,
                              void* d_out, int out_size)
{
    const bool dictOrder = (in_sizes[14] == 2 * DINN * DSTt);

    const float* x          = (const float*)d_in[0];
    const float* abcde_feat = (const float*)d_in[1];
    const float* patch_w    = (const float*)d_in[2];
    const float* patch_b    = (const float*)d_in[3];
    const float* pos_embed  = (const float*)d_in[4];
    const float* abcde_w    = (const float*)d_in[5];
    const float* abcde_b    = (const float*)d_in[6];
    const float* ln_w       = (const float*)d_in[7];
    const float* ln_b       = (const float*)d_in[8];
    const float* in_proj_w  = (const float*)d_in[9];
    const float* conv_w     = (const float*)d_in[10];
    const float* conv_b     = (const float*)d_in[11];
    const float* x_proj_w   = (const float*)d_in[12];
    const float* dt_proj_w  = (const float*)d_in[13];
    const float* dt_proj_b  = dictOrder ? (const float*)d_in[21] : (const float*)d_in[14];
    const float* A_log      = dictOrder ? (const float*)d_in[14] : (const float*)d_in[15];
    const float* D_param    = dictOrder ? (const float*)d_in[15] : (const float*)d_in[16];
    const float* out_proj_w = dictOrder ? (const float*)d_in[16] : (const float*)d_in[17];
    const float* proj_w     = dictOrder ? (const float*)d_in[17] : (const float*)d_in[18];
    const float* proj_b     = dictOrder ? (const float*)d_in[18] : (const float*)d_in[19];
    const float* norm_w     = dictOrder ? (const float*)d_in[19] : (const float*)d_in[20];
    const float* norm_b     = dictOrder ? (const float*)d_in[20] : (const float*)d_in[21];

    float* out = (float*)d_out;

    float *p_xm, *p_xr, *p_xs, *p_dbl, *p_dt, *p_xe, *p_xp, *p_split;
    cudaGetSymbolAddress((void**)&p_xm,  g_xm);
    cudaGetSymbolAddress((void**)&p_xr,  g_xr);
    cudaGetSymbolAddress((void**)&p_xs,  g_xs);
    cudaGetSymbolAddress((void**)&p_dbl, g_dbl);
    cudaGetSymbolAddress((void**)&p_dt,  g_dt);
    cudaGetSymbolAddress((void**)&p_xe,  g_xe);
    cudaGetSymbolAddress((void**)&p_xp,  g_xp);
    cudaGetSymbolAddress((void**)&p_split, g_split);
    __half *ph_col, *ph_xln, *ph_xs, *ph_dbl, *ph_y, *ph_xm;
    __half *ph_patchw, *ph_inw, *ph_xpw, *ph_dtw, *ph_outw, *ph_projw;
    cudaGetSymbolAddress((void**)&ph_col, h_col);
    cudaGetSymbolAddress((void**)&ph_xln, h_xln);
    cudaGetSymbolAddress((void**)&ph_xs,  h_xs);
    cudaGetSymbolAddress((void**)&ph_dbl, h_dbl);
    cudaGetSymbolAddress((void**)&ph_y,   h_y);
    cudaGetSymbolAddress((void**)&ph_xm,  h_xm);
    cudaGetSymbolAddress((void**)&ph_patchw, h_patchw);
    cudaGetSymbolAddress((void**)&ph_inw,  h_inw);
    cudaGetSymbolAddress((void**)&ph_xpw,  h_xpw);
    cudaGetSymbolAddress((void**)&ph_dtw,  h_dtw);
    cudaGetSymbolAddress((void**)&ph_outw, h_outw);
    cudaGetSymbolAddress((void**)&ph_projw, h_projw);

    cudaFuncSetAttribute(tc_gemm_nt, cudaFuncAttributeMaxDynamicSharedMemorySize, SMEMSZ);

    // 0. fused weight conversion
    f2h_all_kernel<<<2048, 256>>>(patch_w, in_proj_w, x_proj_w, dt_proj_w, out_proj_w, proj_w,
                                  ph_patchw, ph_inw, ph_xpw, ph_dtw, ph_outw, ph_projw);

    // 1. index tables
    compute_indices_kernel<<<1, 256>>>();

    // 2. patch embedding (split-K 4) + fused pos/ab/gather
    im2col_kernel<<<(MROWS * EMBED + 255) / 256, 256>>>(x);
    launch_gemm(ph_col, EMBED, ph_patchw, p_split, nullptr,
                MROWS, EMBED, EMBED, nullptr, 0, 0, 4);
    reduce_split_kernel<<<(MROWS * EMBED + 255) / 256, 256>>>(
        p_split, p_xe, nullptr, patch_b, 4, MROWS * EMBED, EMBED);
    gather_fused_kernel<<<(MROWS * DIMM + 255) / 256, 256>>>(pos_embed, abcde_feat, abcde_w, abcde_b);

    // 3. mamba layers
    for (int l = 0; l < 2; l++) {
        const __half* w_in  = ph_inw  + (size_t)l * 2 * DINN * DIMM;
        const float*  w_cv  = conv_w  + (size_t)l * DINN * DCONV;
        const float*  b_cv  = conv_b  + (size_t)l * DINN;
        const __half* w_xp  = ph_xpw  + (size_t)l * XPROJ_N * DINN;
        const __half* w_dt  = ph_dtw  + (size_t)l * DINN * DTRr;
        const float*  b_dt  = dt_proj_b + (size_t)l * DINN;
        const __half* w_out = ph_outw + (size_t)l * DIMM * DINN;
        const float*  Al    = A_log   + (size_t)l * DINN * DSTt;
        const float*  Dl    = D_param + (size_t)l * DINN;

        ln_kernel<<<MROWS, 256>>>(p_xm, nullptr, ph_xln,
                                  ln_w + l * DIMM, ln_b + l * DIMM, DIMM);

        // in_proj: [392,3072] x [12288,3072]^T -> fp32 xr
        launch_gemm(ph_xln, DIMM, w_in, p_xr, nullptr,
                    MROWS, 2 * DINN, DIMM, nullptr, 0, 0);

        conv_silu_kernel<<<(MROWS * DINN + 255) / 256, 256>>>(w_cv, b_cv);

        // x_proj: split-K 8 -> reduce -> dbl (fp32 + fp16)
        launch_gemm(ph_xs, DINN, w_xp, p_split, nullptr,
                    MROWS, XPROJ_N, DINN, nullptr, 0, 0, 8);
        reduce_split_kernel<<<(MROWS * XPROJ_N + 255) / 256, 256>>>(
            p_split, p_dbl, ph_dbl, nullptr, 8, MROWS * XPROJ_N, XPROJ_N);

        // dt_proj + bias + softplus -> fp32 dt   (K=192 -> 6 k32 stages)
        launch_gemm(ph_dbl, XPROJ_N, w_dt, p_dt, nullptr,
                    MROWS, DINN, DTRr, b_dt, 1, 0);

        scan_kernel<<<(BATCH * DINN * DSTt) / 256, 256>>>(Al, Dl);

        // out_proj + residual accumulate into xm (+ fp16 mirror)
        launch_gemm(ph_y, DINN, w_out, p_xm, ph_xm,
                    MROWS, DIMM, DINN, nullptr, 0, 1);
    }

    // 4. final projection (split-K 4) + LN + mean
    launch_gemm(ph_xm, DIMM, ph_projw, p_split, nullptr,
                MROWS, EMBED, DIMM, nullptr, 0, 0, 4);
    reduce_split_kernel<<<(MROWS * EMBED + 255) / 256, 256>>>(
        p_split, p_xp, nullptr, proj_b, 4, MROWS * EMBED, EMBED);
    ln_kernel<<<MROWS, 256>>>(p_xp, p_xp, nullptr, norm_w, norm_b, EMBED);
    mean_kernel<<<(BATCH * EMBED + 255) / 256, 256>>>(out);

    (void)n_in; (void)out_size;
}

// round 16
// speedup vs baseline: 1.2988x; 1.0183x over previous
#include <cuda_runtime.h>
#include <cuda_fp16.h>
#include <math.h>
#include <stdint.h>

// ---------------- problem constants ----------------
#define HH      14
#define LL      196            // H*W
#define EMBED   768
#define DIMM    3072           // 4*EMBED
#define DINN    6144           // 2*DIM
#define DTRr    192
#define DSTt    16
#define DCONV   4
#define BATCH   2
#define MROWS   392            // BATCH*LL
#define XPROJ_N 224            // DTR + 2*DST

// ---------------- fp32 scratch ----------------
__device__ float g_xe [MROWS * EMBED];
__device__ float g_xm [MROWS * DIMM];
__device__ float g_xr [MROWS * 2 * DINN];
__device__ float g_xs [MROWS * DINN];
__device__ float g_dbl[MROWS * XPROJ_N];
__device__ float g_dt [MROWS * DINN];
__device__ float g_xp [MROWS * EMBED];
__device__ float g_split[8 * MROWS * 768];   // split-K partials
__device__ int   g_sp[LL];
__device__ int   g_ra[LL];
__device__ int   g_bd[LL];

// ---------------- fp16 activation mirrors (GEMM A-operands) ----------------
__device__ __half h_col [MROWS * EMBED];
__device__ __half h_xln [MROWS * DIMM];
__device__ __half h_xs  [MROWS * DINN];
__device__ __half h_dbl [MROWS * XPROJ_N];
__device__ __half h_y   [MROWS * DINN];
__device__ __half h_xm  [MROWS * DIMM];
// fp16 weights
__device__ __half h_patchw[EMBED * EMBED];
__device__ __half h_inw  [2 * 2 * DINN * DIMM];
__device__ __half h_xpw  [2 * XPROJ_N * DINN];
__device__ __half h_dtw  [2 * DINN * DTRr];
__device__ __half h_outw [2 * DIMM * DINN];
__device__ __half h_projw[EMBED * DIMM];

// ---------------- helpers ----------------
__device__ __forceinline__ float sigmoidf_(float v) { return 1.0f / (1.0f + expf(-v)); }
__device__ __forceinline__ float softplusf_(float v) {
    return v > 0.0f ? v + log1pf(expf(-v)) : log1pf(expf(v));
}
__device__ __forceinline__ void mma_f16(float* c, const uint32_t* a, const uint32_t* b) {
    asm volatile(
        "mma.sync.aligned.m16n8k16.row.col.f32.f16.f16.f32 "
        "{%0,%1,%2,%3}, {%4,%5,%6,%7}, {%8,%9}, {%0,%1,%2,%3};"
        : "+f"(c[0]), "+f"(c[1]), "+f"(c[2]), "+f"(c[3])
        : "r"(a[0]), "r"(a[1]), "r"(a[2]), "r"(a[3]), "r"(b[0]), "r"(b[1]));
}
__device__ __forceinline__ void ldsm4(uint32_t& r0, uint32_t& r1, uint32_t& r2, uint32_t& r3,
                                      uint32_t addr) {
    asm volatile("ldmatrix.sync.aligned.m8n8.x4.shared.b16 {%0,%1,%2,%3}, [%4];"
                 : "=r"(r0), "=r"(r1), "=r"(r2), "=r"(r3) : "r"(addr));
}
__device__ __forceinline__ void cp_async16(uint32_t dst, const __half* src) {
    asm volatile("cp.async.ca.shared.global [%0], [%1], 16;"
                 :: "r"(dst), "l"(__cvta_generic_to_global(src)) : "memory");
}
__device__ __forceinline__ void cp_commit() {
    asm volatile("cp.async.commit_group;" ::: "memory");
}
__device__ __forceinline__ void cp_wait1() {
    asm volatile("cp.async.wait_group 1;" ::: "memory");
}

// ================= fp16 tensor-core GEMM, k32 stages, 3-deep cp.async =================
// C[M,N] = A[M,K] * B[N,K]^T. tile TM x 128 x k32; 256 thr = 8 warps (2M x 4N).
// TM in {128, 64}. m0 = row offset of this launch. split-K via gridDim.z.
#define TNt 128
#define NST 3
#define HPITCH 40                          // halves per smem row (80B), conflict-free ldmatrix
#define BTILE_B (128 * HPITCH * 2)         // B tile: 10240 B
#define SM_OF(TM) (NST * ((TM) * HPITCH * 2 + BTILE_B))

template<int TM>
__global__ __launch_bounds__(256, 2)
void tc_gemm_nt(const __half* __restrict__ A, int lda,
                const __half* __restrict__ B,
                float* __restrict__ C, __half* __restrict__ Ch,
                int M, int N, int K,
                const float* __restrict__ bias,
                int act, int beta, int m0)
{
    constexpr int WM  = TM / 2;            // warp M span
    constexpr int MI  = WM / 16;           // m16 fragments per warp
    constexpr int ATILE = TM * HPITCH * 2; // bytes
    constexpr int STG   = ATILE + BTILE_B;

    extern __shared__ char smem[];
    const uint32_t sbase = (uint32_t)__cvta_generic_to_shared(smem);
    const int tid  = threadIdx.x;
    const int wid  = tid >> 5;
    const int lane = tid & 31;
    const int g = lane >> 2;
    const int t = lane & 3;
    const int bm0 = m0 + blockIdx.y * TM;
    const int bn0 = blockIdx.x * TNt;
    const int wm0 = (wid >> 2) * WM;
    const int wn0 = (wid & 3) * 32;

    const int kchunk = K / gridDim.z;
    const int koff   = blockIdx.z * kchunk;
    const int ns     = kchunk >> 5;        // k32 stages
    C += (size_t)blockIdx.z * M * N;

    // ldmatrix lane offsets (bytes within operand tile)
    const int q  = lane >> 3;
    const int ri = lane & 7;
    uint32_t aoff[MI], boff[2];
#pragma unroll
    for (int mi = 0; mi < MI; mi++)
        aoff[mi] = (uint32_t)(((wm0 + mi * 16 + (q & 1) * 8 + ri) * HPITCH + (q >> 1) * 8) * 2);
#pragma unroll
    for (int nj = 0; nj < 2; nj++)
        boff[nj] = (uint32_t)(((wn0 + nj * 16 + (q >> 1) * 8 + ri) * HPITCH + (q & 1) * 8) * 2);

    // cp.async mapping: 2 threads per row, 16 halves (2x16B) each; rows >= TM skip A.
    const int lrow = tid >> 1;
    const int lk16 = (tid & 1) * 16;
    const bool hasA = (lrow < TM);
    int ar = bm0 + lrow; if (ar > M - 1) ar = M - 1;
    int br = bn0 + lrow; if (br > N - 1) br = N - 1;
    const __half* pa = A + (size_t)ar * lda + koff + lk16;
    const __half* pb = B + (size_t)br * K + koff + lk16;
    const uint32_t soff = (uint32_t)((lrow * HPITCH + lk16) * 2);

    auto issue = [&](int s) {
        const uint32_t base = sbase + (uint32_t)(s % NST) * STG;
        if (hasA) {
            cp_async16(base + soff,      pa + s * 32);
            cp_async16(base + soff + 16, pa + s * 32 + 8);
        }
        cp_async16(base + ATILE + soff,      pb + s * 32);
        cp_async16(base + ATILE + soff + 16, pb + s * 32 + 8);
        cp_commit();
    };

    float c[MI][4][4];
#pragma unroll
    for (int mi = 0; mi < MI; mi++)
#pragma unroll
        for (int ni = 0; ni < 4; ni++)
#pragma unroll
            for (int r = 0; r < 4; r++) c[mi][ni][r] = 0.0f;

#pragma unroll
    for (int s = 0; s < NST - 1; s++) {
        if (s < ns) issue(s); else cp_commit();
    }

    for (int s = 0; s < ns; s++) {
        cp_wait1();
        __syncthreads();
        if (s + NST - 1 < ns) issue(s + NST - 1); else cp_commit();

        const uint32_t abase = sbase + (uint32_t)(s % NST) * STG;
        const uint32_t bbase = abase + ATILE;
#pragma unroll
        for (int ka = 0; ka < 2; ka++) {
            const uint32_t ko = (uint32_t)(ka * 32);   // 16 halves
            uint32_t a[MI][4], b[4][2];
#pragma unroll
            for (int mi = 0; mi < MI; mi++)
                ldsm4(a[mi][0], a[mi][1], a[mi][2], a[mi][3], abase + aoff[mi] + ko);
#pragma unroll
            for (int nj = 0; nj < 2; nj++) {
                uint32_t r0, r1, r2, r3;
                ldsm4(r0, r1, r2, r3, bbase + boff[nj] + ko);
                b[2 * nj][0] = r0; b[2 * nj][1] = r1;
                b[2 * nj + 1][0] = r2; b[2 * nj + 1][1] = r3;
            }
#pragma unroll
            for (int mi = 0; mi < MI; mi++)
#pragma unroll
                for (int ni = 0; ni < 4; ni++)
                    mma_f16(c[mi][ni], a[mi], b[ni]);
        }
    }

    // epilogue: float2 / half2 stores
#pragma unroll
    for (int mi = 0; mi < MI; mi++) {
        const int row0 = bm0 + wm0 + mi * 16 + g;
#pragma unroll
        for (int ni = 0; ni < 4; ni++) {
            const int col = bn0 + wn0 + ni * 8 + 2 * t;
            if (col >= N) continue;
#pragma unroll
            for (int h = 0; h < 2; h++) {
                const int row = row0 + 8 * h;
                if (row >= M) continue;
                float v0 = c[mi][ni][2 * h];
                float v1 = c[mi][ni][2 * h + 1];
                if (bias) { v0 += bias[col]; v1 += bias[col + 1]; }
                if (act == 1) { v0 = softplusf_(v0); v1 = softplusf_(v1); }
                float2* p = reinterpret_cast<float2*>(C + (size_t)row * N + col);
                if (beta) { float2 o = *p; v0 += o.x; v1 += o.y; }
                *p = make_float2(v0, v1);
                if (Ch)
                    *reinterpret_cast<__half2*>(Ch + (size_t)row * N + col) =
                        __floats2half2_rn(v0, v1);
            }
        }
    }
}

// ---------------- split-K reduce (+bias, + fp16 mirror) ----------------
__global__ void reduce_split_kernel(const float* __restrict__ sp,
                                    float* __restrict__ C, __half* __restrict__ Ch,
                                    const float* __restrict__ bias,
                                    int nsplit, int MN, int N)
{
    int idx = blockIdx.x * blockDim.x + threadIdx.x;
    if (idx >= MN) return;
    float s = 0.0f;
    for (int i = 0; i < nsplit; i++) s += sp[(size_t)i * MN + idx];
    if (bias) s += bias[idx % N];
    C[idx] = s;
    if (Ch) Ch[idx] = __float2half(s);
}

// ---------------- fused fp32->fp16 weight conversion (all 6 tensors, 1 launch) ----------------
#define U_PATCH ((EMBED * EMBED) / 8)
#define U_IN    ((2 * 2 * DINN * DIMM) / 8)
#define U_XP    ((2 * XPROJ_N * DINN) / 8)
#define U_DT    ((2 * DINN * DTRr) / 8)
#define U_OUT   ((2 * DIMM * DINN) / 8)
#define U_PROJ  ((EMBED * DIMM) / 8)
#define C0 U_PATCH
#define C1 (C0 + U_IN)
#define C2 (C1 + U_XP)
#define C3 (C2 + U_DT)
#define C4 (C3 + U_OUT)
#define C5 (C4 + U_PROJ)

__global__ void f2h_all_kernel(const float* __restrict__ s0, const float* __restrict__ s1,
                               const float* __restrict__ s2, const float* __restrict__ s3,
                               const float* __restrict__ s4, const float* __restrict__ s5,
                               __half* __restrict__ d0, __half* __restrict__ d1,
                               __half* __restrict__ d2, __half* __restrict__ d3,
                               __half* __restrict__ d4, __half* __restrict__ d5)
{
    const long stride = (long)gridDim.x * blockDim.x;
    auto unit = [&](long u) {
        const float* s; __half* d; long o;
        if      (u < C0) { s = s0; d = d0; o = u; }
        else if (u < C1) { s = s1; d = d1; o = u - C0; }
        else if (u < C2) { s = s2; d = d2; o = u - C1; }
        else if (u < C3) { s = s3; d = d3; o = u - C2; }
        else if (u < C4) { s = s4; d = d4; o = u - C3; }
        else             { s = s5; d = d5; o = u - C4; }
        const float4* p = reinterpret_cast<const float4*>(s) + 2 * o;
        float4 a = p[0], b = p[1];
        __half2 h[4];
        h[0] = __floats2half2_rn(a.x, a.y); h[1] = __floats2half2_rn(a.z, a.w);
        h[2] = __floats2half2_rn(b.x, b.y); h[3] = __floats2half2_rn(b.z, b.w);
        reinterpret_cast<uint4*>(d)[o] = *reinterpret_cast<uint4*>(h);
    };
    long u = (long)blockIdx.x * blockDim.x + threadIdx.x;
    for (; u + 3 * stride < C5; u += 4 * stride) {
        unit(u); unit(u + stride); unit(u + 2 * stride); unit(u + 3 * stride);
    }
    for (; u < C5; u += stride) unit(u);
}

// ---------------- index tables (numpy double-precision exact) ----------------
__global__ void compute_indices_kernel() {
    __shared__ double sdd[LL];
    __shared__ double saa[LL];
    __shared__ int    cand[202];
    __shared__ unsigned char seen[LL];
    const int tid = threadIdx.x;
    const double TWO_PI = 2.0 * 3.14159265358979323846;

    if (tid < 202) {
        int r = 0, rem = tid;
        for (;;) {
            int c = (2 * r > 8) ? 2 * r : 8;
            if (rem < c) break;
            rem -= c; r++;
        }
        int nang = (2 * r > 8) ? 2 * r : 8;
        double step = TWO_PI / (double)nang;
        double ang = (double)rem * step;
        double hh = 7.0 + (double)r * cos(ang);
        double ww = 7.0 + (double)r * sin(ang);
        int h = (int)hh;
        int w = (int)ww;
        cand[tid] = (h >= 0 && h < HH && w >= 0 && w < HH) ? (h * HH + w) : -1;
    }
    if (tid < LL) {
        seen[tid] = 0;
        int h = tid / HH, w = tid % HH;
        double dy = (double)(h - 7), dx = (double)(w - 7);
        sdd[tid] = sqrt(dy * dy + dx * dx);
        saa[tid] = atan2(dy, dx);
    }
    __syncthreads();

    if (tid == 0) {
        int cnt = 0;
        for (int i = 0; i < 202; i++) {
            int c = cand[i];
            if (c >= 0 && !seen[c]) { seen[c] = 1; g_sp[cnt++] = c; }
        }
        for (int i = 0; i < LL; i++)
            if (!seen[i]) g_sp[cnt++] = i;
        int bc = 0;
        for (int i = 0; i < LL; i++) {
            int h = i / HH, w = i % HH;
            if (h == 0 || h == HH - 1 || w == 0 || w == HH - 1) g_bd[bc++] = i;
        }
        for (int i = 0; i < LL; i++) {
            int h = i / HH, w = i % HH;
            if (!(h == 0 || h == HH - 1 || w == 0 || w == HH - 1)) g_bd[bc++] = i;
        }
    }
    if (tid < LL) {
        double di = sdd[tid], ai = saa[tid];
        int rank = 0;
        for (int j = 0; j < LL; j++) {
            double dj = sdd[j], aj = saa[j];
            bool before = (dj > di) ||
                          (dj == di && (aj < ai || (aj == ai && j < tid)));
            rank += before ? 1 : 0;
        }
        g_ra[rank] = tid;
    }
}

// ---------------- im2col (fp16 out) ----------------
__global__ void im2col_kernel(const float* __restrict__ x) {
    int idx = blockIdx.x * blockDim.x + threadIdx.x;
    if (idx >= MROWS * EMBED) return;
    int m = idx / EMBED;
    int k = idx % EMBED;
    int b = m / LL, l = m % LL;
    int ph = l / HH, pw = l % HH;
    int c = k / 256, rem = k % 256;
    int i = rem / 16, j = rem % 16;
    h_col[idx] = __float2half(
        x[(((size_t)(b * 3 + c) * 224) + (ph * 16 + i)) * 224 + (pw * 16 + j)]);
}

// ---------------- fused gather: xm = concat4(xe[perm] + pos[perm] + ab) ----------------
__global__ void gather_fused_kernel(const float* __restrict__ pos_embed,
                                    const float* __restrict__ abcde_features,
                                    const float* __restrict__ abcde_w,
                                    const float* __restrict__ abcde_b)
{
    int idx = blockIdx.x * blockDim.x + threadIdx.x;
    if (idx >= MROWS * DIMM) return;
    int m = idx / DIMM;
    int c = idx % DIMM;
    int b = m / LL, l = m % LL;
    int s = c / EMBED, e = c % EMBED;
    int src_l = (s == 0) ? g_sp[l] : (s == 1) ? g_ra[l] : (s == 2) ? g_bd[l] : l;
    float ab = abcde_b[e];
#pragma unroll
    for (int k = 0; k < 5; k++)
        ab += abcde_features[b * 5 + k] * abcde_w[e * 5 + k];
    g_xm[idx] = g_xe[((size_t)(b * LL + src_l)) * EMBED + e]
              + pos_embed[src_l * EMBED + e] + ab;
}

// ---------------- layernorm (fp32 in; optional fp32 / fp16 outs) ----------------
__global__ void ln_kernel(const float* __restrict__ in,
                          float* __restrict__ out_f, __half* __restrict__ out_h,
                          const float* __restrict__ w, const float* __restrict__ b,
                          int width)
{
    __shared__ float red[256];
    __shared__ float s_mean, s_rstd;
    const int row = blockIdx.x;
    const float* x = in + (size_t)row * width;
    float s = 0.0f;
    for (int j = threadIdx.x; j < width; j += 256) s += x[j];
    red[threadIdx.x] = s; __syncthreads();
    for (int off = 128; off > 0; off >>= 1) {
        if (threadIdx.x < off) red[threadIdx.x] += red[threadIdx.x + off];
        __syncthreads();
    }
    if (threadIdx.x == 0) s_mean = red[0] / (float)width;
    __syncthreads();
    float m = s_mean;
    float vs = 0.0f;
    for (int j = threadIdx.x; j < width; j += 256) {
        float d = x[j] - m; vs += d * d;
    }
    red[threadIdx.x] = vs; __syncthreads();
    for (int off = 128; off > 0; off >>= 1) {
        if (threadIdx.x < off) red[threadIdx.x] += red[threadIdx.x + off];
        __syncthreads();
    }
    if (threadIdx.x == 0) s_rstd = rsqrtf(red[0] / (float)width + 1e-5f);
    __syncthreads();
    float r = s_rstd;
    for (int j = threadIdx.x; j < width; j += 256) {
        float v = (x[j] - m) * r * w[j] + b[j];
        if (out_f) out_f[(size_t)row * width + j] = v;
        if (out_h) out_h[(size_t)row * width + j] = __float2half(v);
    }
}

// ---------------- causal depthwise conv + bias + silu (fp32 + fp16 out) ----------------
__global__ void conv_silu_kernel(const float* __restrict__ conv_w,
                                 const float* __restrict__ conv_b)
{
    int idx = blockIdx.x * blockDim.x + threadIdx.x;
    if (idx >= MROWS * DINN) return;
    int row = idx / DINN;
    int d   = idx % DINN;
    int b = row / LL, t = row % LL;
    float acc = conv_b[d];
#pragma unroll
    for (int j = 0; j < DCONV; j++) {
        int tt = t - (DCONV - 1) + j;
        if (tt >= 0)
            acc += conv_w[d * DCONV + j] * g_xr[((size_t)(b * LL + tt)) * (2 * DINN) + d];
    }
    float v = acc * sigmoidf_(acc);
    g_xs[idx] = v;
    h_xs[idx] = __float2half(v);
}

// ---------------- selective scan: 4 states per thread, width-4 shfl reduce ----------------
__global__ void scan_kernel(const float* __restrict__ A_log,
                            const float* __restrict__ D_param)
{
    const int gid = blockIdx.x * blockDim.x + threadIdx.x;   // 2*6144*4 threads
    const int nq = gid & 3;            // state quad (4 states each)
    const int dg = gid >> 2;
    const int d  = dg % DINN;
    const int b  = dg / DINN;

    float Al[4];
#pragma unroll
    for (int j = 0; j < 4; j++)
        Al[j] = -expf(A_log[d * DSTt + nq * 4 + j]) * 1.4426950408889634f;
    const float Dd = D_param[d];

    float s0 = 0.f, s1 = 0.f, s2 = 0.f, s3 = 0.f;
#pragma unroll 1
    for (int t = 0; t < LL; t++) {
        const size_t row = (size_t)(b * LL + t);
        const float dtv = g_dt[row * DINN + d];
        const float xv  = g_xs[row * DINN + d];
        const float4 Bv = *reinterpret_cast<const float4*>(
            &g_dbl[row * XPROJ_N + DTRr + nq * 4]);
        const float4 Cv = *reinterpret_cast<const float4*>(
            &g_dbl[row * XPROJ_N + DTRr + DSTt + nq * 4]);
        const float dx = dtv * xv;
        s0 = s0 * exp2f(dtv * Al[0]) + dx * Bv.x;
        s1 = s1 * exp2f(dtv * Al[1]) + dx * Bv.y;
        s2 = s2 * exp2f(dtv * Al[2]) + dx * Bv.z;
        s3 = s3 * exp2f(dtv * Al[3]) + dx * Bv.w;
        float p = s0 * Cv.x + s1 * Cv.y + s2 * Cv.z + s3 * Cv.w;
        p += __shfl_xor_sync(0xffffffffu, p, 1, 4);
        p += __shfl_xor_sync(0xffffffffu, p, 2, 4);
        if (nq == 0) {
            float res = g_xr[row * (2 * DINN) + DINN + d];
            float y = (p + xv * Dd) * (res * sigmoidf_(res));
            h_y[row * DINN + d] = __float2half(y);
        }
    }
}

// ---------------- final mean over L ----------------
__global__ void mean_kernel(float* __restrict__ out) {
    int idx = blockIdx.x * blockDim.x + threadIdx.x;
    if (idx >= BATCH * EMBED) return;
    int b = idx / EMBED, e = idx % EMBED;
    float s = 0.0f;
    for (int l = 0; l < LL; l++)
        s += g_xp[((size_t)(b * LL + l)) * EMBED + e];
    out[idx] = s / (float)LL;
}

// ---------------- host helpers ----------------
// big GEMM (M=392): TM128 rows 0..383 + TM64 remainder rows 384..391
static inline void launch_gemm_big(const __half* A, int lda, const __half* B,
                                   float* C, __half* Ch, int N, int K,
                                   const float* bias, int act, int beta)
{
    dim3 g1((N + TNt - 1) / TNt, 3, 1);
    tc_gemm_nt<128><<<g1, 256, SM_OF(128)>>>(A, lda, B, C, Ch, MROWS, N, K, bias, act, beta, 0);
    dim3 g2((N + TNt - 1) / TNt, 1, 1);
    tc_gemm_nt<64><<<g2, 256, SM_OF(64)>>>(A, lda, B, C, Ch, MROWS, N, K, bias, act, beta, 384);
}
// small GEMM: pure TM64, y=7 covers 448 rows
static inline void launch_gemm_small(const __half* A, int lda, const __half* B,
                                     float* C, __half* Ch, int N, int K,
                                     const float* bias, int act, int beta, int splitk = 1)
{
    dim3 grid((N + TNt - 1) / TNt, 7, splitk);
    tc_gemm_nt<64><<<grid, 256, SM_OF(64)>>>(A, lda, B, C, Ch, MROWS, N, K, bias, act, beta, 0);
}

extern "C" void kernel_launch(void* const* d_in, const int* in_sizes, int n_in,
                              void* d_out, int out_size)
{
    const bool dictOrder = (in_sizes[14] == 2 * DINN * DSTt);

    const float* x          = (const float*)d_in[0];
    const float* abcde_feat = (const float*)d_in[1];
    const float* patch_w    = (const float*)d_in[2];
    const float* patch_b    = (const float*)d_in[3];
    const float* pos_embed  = (const float*)d_in[4];
    const float* abcde_w    = (const float*)d_in[5];
    const float* abcde_b    = (const float*)d_in[6];
    const float* ln_w       = (const float*)d_in[7];
    const float* ln_b       = (const float*)d_in[8];
    const float* in_proj_w  = (const float*)d_in[9];
    const float* conv_w     = (const float*)d_in[10];
    const float* conv_b     = (const float*)d_in[11];
    const float* x_proj_w   = (const float*)d_in[12];
    const float* dt_proj_w  = (const float*)d_in[13];
    const float* dt_proj_b  = dictOrder ? (const float*)d_in[21] : (const float*)d_in[14];
    const float* A_log      = dictOrder ? (const float*)d_in[14] : (const float*)d_in[15];
    const float* D_param    = dictOrder ? (const float*)d_in[15] : (const float*)d_in[16];
    const float* out_proj_w = dictOrder ? (const float*)d_in[16] : (const float*)d_in[17];
    const float* proj_w     = dictOrder ? (const float*)d_in[17] : (const float*)d_in[18];
    const float* proj_b     = dictOrder ? (const float*)d_in[18] : (const float*)d_in[19];
    const float* norm_w     = dictOrder ? (const float*)d_in[19] : (const float*)d_in[20];
    const float* norm_b     = dictOrder ? (const float*)d_in[20] : (const float*)d_in[21];

    float* out = (float*)d_out;

    float *p_xm, *p_xr, *p_xs, *p_dbl, *p_dt, *p_xe, *p_xp, *p_split;
    cudaGetSymbolAddress((void**)&p_xm,  g_xm);
    cudaGetSymbolAddress((void**)&p_xr,  g_xr);
    cudaGetSymbolAddress((void**)&p_xs,  g_xs);
    cudaGetSymbolAddress((void**)&p_dbl, g_dbl);
    cudaGetSymbolAddress((void**)&p_dt,  g_dt);
    cudaGetSymbolAddress((void**)&p_xe,  g_xe);
    cudaGetSymbolAddress((void**)&p_xp,  g_xp);
    cudaGetSymbolAddress((void**)&p_split, g_split);
    __half *ph_col, *ph_xln, *ph_xs, *ph_dbl, *ph_y, *ph_xm;
    __half *ph_patchw, *ph_inw, *ph_xpw, *ph_dtw, *ph_outw, *ph_projw;
    cudaGetSymbolAddress((void**)&ph_col, h_col);
    cudaGetSymbolAddress((void**)&ph_xln, h_xln);
    cudaGetSymbolAddress((void**)&ph_xs,  h_xs);
    cudaGetSymbolAddress((void**)&ph_dbl, h_dbl);
    cudaGetSymbolAddress((void**)&ph_y,   h_y);
    cudaGetSymbolAddress((void**)&ph_xm,  h_xm);
    cudaGetSymbolAddress((void**)&ph_patchw, h_patchw);
    cudaGetSymbolAddress((void**)&ph_inw,  h_inw);
    cudaGetSymbolAddress((void**)&ph_xpw,  h_xpw);
    cudaGetSymbolAddress((void**)&ph_dtw,  h_dtw);
    cudaGetSymbolAddress((void**)&ph_outw, h_outw);
    cudaGetSymbolAddress((void**)&ph_projw, h_projw);

    cudaFuncSetAttribute(tc_gemm_nt<128>, cudaFuncAttributeMaxDynamicSharedMemorySize, SM_OF(128));
    cudaFuncSetAttribute(tc_gemm_nt<64>,  cudaFuncAttributeMaxDynamicSharedMemorySize, SM_OF(64));

    // 0. fused weight conversion
    f2h_all_kernel<<<2048, 256>>>(patch_w, in_proj_w, x_proj_w, dt_proj_w, out_proj_w, proj_w,
                                  ph_patchw, ph_inw, ph_xpw, ph_dtw, ph_outw, ph_projw);

    // 1. index tables
    compute_indices_kernel<<<1, 256>>>();

    // 2. patch embedding (TM64, split-K 4) + fused pos/ab/gather
    im2col_kernel<<<(MROWS * EMBED + 255) / 256, 256>>>(x);
    launch_gemm_small(ph_col, EMBED, ph_patchw, p_split, nullptr,
                      EMBED, EMBED, nullptr, 0, 0, 4);
    reduce_split_kernel<<<(MROWS * EMBED + 255) / 256, 256>>>(
        p_split, p_xe, nullptr, patch_b, 4, MROWS * EMBED, EMBED);
    gather_fused_kernel<<<(MROWS * DIMM + 255) / 256, 256>>>(pos_embed, abcde_feat, abcde_w, abcde_b);

    // 3. mamba layers
    for (int l = 0; l < 2; l++) {
        const __half* w_in  = ph_inw  + (size_t)l * 2 * DINN * DIMM;
        const float*  w_cv  = conv_w  + (size_t)l * DINN * DCONV;
        const float*  b_cv  = conv_b  + (size_t)l * DINN;
        const __half* w_xp  = ph_xpw  + (size_t)l * XPROJ_N * DINN;
        const __half* w_dt  = ph_dtw  + (size_t)l * DINN * DTRr;
        const float*  b_dt  = dt_proj_b + (size_t)l * DINN;
        const __half* w_out = ph_outw + (size_t)l * DIMM * DINN;
        const float*  Al    = A_log   + (size_t)l * DINN * DSTt;
        const float*  Dl    = D_param + (size_t)l * DINN;

        ln_kernel<<<MROWS, 256>>>(p_xm, nullptr, ph_xln,
                                  ln_w + l * DIMM, ln_b + l * DIMM, DIMM);

        // in_proj: [392,3072] x [12288,3072]^T -> fp32 xr  (TM128 + TM64 remainder)
        launch_gemm_big(ph_xln, DIMM, w_in, p_xr, nullptr,
                        2 * DINN, DIMM, nullptr, 0, 0);

        conv_silu_kernel<<<(MROWS * DINN + 255) / 256, 256>>>(w_cv, b_cv);

        // x_proj: TM64 split-K 8 -> reduce -> dbl (fp32 + fp16)
        launch_gemm_small(ph_xs, DINN, w_xp, p_split, nullptr,
                          XPROJ_N, DINN, nullptr, 0, 0, 8);
        reduce_split_kernel<<<(MROWS * XPROJ_N + 255) / 256, 256>>>(
            p_split, p_dbl, ph_dbl, nullptr, 8, MROWS * XPROJ_N, XPROJ_N);

        // dt_proj + bias + softplus -> fp32 dt (TM64, K=192 -> 6 stages, 336 CTAs)
        launch_gemm_small(ph_dbl, XPROJ_N, w_dt, p_dt, nullptr,
                          DINN, DTRr, b_dt, 1, 0);

        scan_kernel<<<(BATCH * DINN * 4) / 256, 256>>>(Al, Dl);

        // out_proj + residual accumulate into xm (+ fp16 mirror) — TM64, 168 CTAs
        launch_gemm_small(ph_y, DINN, w_out, p_xm, ph_xm,
                          DIMM, DINN, nullptr, 0, 1);
    }

    // 4. final projection (TM64 split-K 4) + LN + mean
    launch_gemm_small(ph_xm, DIMM, ph_projw, p_split, nullptr,
                      EMBED, DIMM, nullptr, 0, 0, 4);
    reduce_split_kernel<<<(MROWS * EMBED + 255) / 256, 256>>>(
        p_split, p_xp, nullptr, proj_b, 4, MROWS * EMBED, EMBED);
    ln_kernel<<<MROWS, 256>>>(p_xp, p_xp, nullptr, norm_w, norm_b, EMBED);
    mean_kernel<<<(BATCH * EMBED + 255) / 256, 256>>>(out);

    (void)n_in; (void)out_size;
}